// round 2
// baseline (speedup 1.0000x reference)
#include <cuda_runtime.h>
#include <math.h>

#define SS 256
#define BB 128
#define II 256
#define HH 512
#define GG 4
#define EPSF 1e-7f

struct Ptrs {
    const float* W[4];   // (H,I) input-projection weights, gate order i,f,o,g
    const float* bx[4];  // (H,) input-projection biases
    const float* U[4];   // (H,H) recurrent weights
    const float* bu[4];  // (H,) recurrent biases
};

// Scratch (static device globals: allocation-free at launch time)
__device__ float g_zx[GG * BB * II];                     // 512 KB
__device__ float g_zh[GG * BB * HH];                     // 1 MB
__device__ float g_hm[GG * BB * HH];                     // 1 MB  (h * zh per gate)
__device__ float g_c[BB * HH];                           // 256 KB (cell state)
__device__ float g_part[2 * GG * BB * HH];               // 2 MB  (split-K partials)
__device__ float g_xproj[(size_t)SS * GG * BB * HH];     // 256 MB

__device__ __forceinline__ float sigf(float x) { return 1.0f / (1.0f + expf(-x)); }

// ---------------------------------------------------------------------------
// Kernel 1: concrete-dropout masks + zero recurrent state (runs every replay)
// ---------------------------------------------------------------------------
__global__ void k_setup(const float* __restrict__ p_logit,
                        const float* __restrict__ ux,
                        const float* __restrict__ uh) {
    float p = sigf(p_logit[0]);
    float logit_p = logf(p + EPSF) - logf(1.0f - p + EPSF);
    float inv1mp = 1.0f / (1.0f - p);
    int stride = gridDim.x * blockDim.x;
    for (int i = blockIdx.x * blockDim.x + threadIdx.x; i < GG * BB * HH; i += stride) {
        float u = uh[i];
        float sg = sigf((logit_p + logf(u + EPSF) - logf(1.0f - u + EPSF)) * 10.0f);
        g_zh[i] = (1.0f - sg) * inv1mp;
        g_hm[i] = 0.0f;  // h0 = 0
        if (i < GG * BB * II) {
            float u2 = ux[i];
            float s2 = sigf((logit_p + logf(u2 + EPSF) - logf(1.0f - u2 + EPSF)) * 10.0f);
            g_zx[i] = (1.0f - s2) * inv1mp;
        }
        if (i < BB * HH) g_c[i] = 0.0f;  // c0 = 0
    }
}

// ---------------------------------------------------------------------------
// Kernel 2: xproj[s,g,b,h] = sum_i x[s,b,i]*zx[g,b,i]*W[g][h,i] + bx[g][h]
// Tile: one s (=128 b-rows) x 128 h-cols, K=256 in chunks of 8, 8x8 microtile.
// grid = (S, H/128, G), 256 threads.
// ---------------------------------------------------------------------------
__global__ __launch_bounds__(256) void k_xproj(const float* __restrict__ x, Ptrs P) {
    int s  = blockIdx.x;
    int n0 = blockIdx.y * 128;
    int g  = blockIdx.z;
    const float* __restrict__ W = P.W[g];

    __shared__ float As[8][132];
    __shared__ float Bs[8][132];

    int tid = threadIdx.x;
    int tx = tid & 15, ty = tid >> 4;
    int lrow = tid >> 1;           // 0..127
    int lcol = (tid & 1) * 4;      // 0 or 4

    const float* xrow = x + ((size_t)s * BB + lrow) * II;
    const float* zrow = g_zx + ((size_t)g * BB + lrow) * II;
    const float* wrow = W + (size_t)(n0 + lrow) * II;

    float acc[8][8];
#pragma unroll
    for (int i = 0; i < 8; i++)
#pragma unroll
        for (int j = 0; j < 8; j++) acc[i][j] = 0.0f;

    for (int i0 = 0; i0 < II; i0 += 8) {
        float4 xa = *(const float4*)(xrow + i0 + lcol);
        float4 za = *(const float4*)(zrow + i0 + lcol);
        float4 wb = *(const float4*)(wrow + i0 + lcol);
        As[lcol + 0][lrow] = xa.x * za.x;
        As[lcol + 1][lrow] = xa.y * za.y;
        As[lcol + 2][lrow] = xa.z * za.z;
        As[lcol + 3][lrow] = xa.w * za.w;
        Bs[lcol + 0][lrow] = wb.x;
        Bs[lcol + 1][lrow] = wb.y;
        Bs[lcol + 2][lrow] = wb.z;
        Bs[lcol + 3][lrow] = wb.w;
        __syncthreads();
#pragma unroll
        for (int kc = 0; kc < 8; kc++) {
            float4 a0 = *(const float4*)&As[kc][ty * 4];
            float4 a1 = *(const float4*)&As[kc][64 + ty * 4];
            float4 b0 = *(const float4*)&Bs[kc][tx * 4];
            float4 b1 = *(const float4*)&Bs[kc][64 + tx * 4];
            float a[8] = {a0.x, a0.y, a0.z, a0.w, a1.x, a1.y, a1.z, a1.w};
            float b[8] = {b0.x, b0.y, b0.z, b0.w, b1.x, b1.y, b1.z, b1.w};
#pragma unroll
            for (int i = 0; i < 8; i++)
#pragma unroll
                for (int j = 0; j < 8; j++) acc[i][j] += a[i] * b[j];
        }
        __syncthreads();
    }

    // epilogue: add bias, store to g_xproj[s][g][b][h]
    const float* bias = P.bx[g];
    int rows[8], cols[8];
#pragma unroll
    for (int i = 0; i < 4; i++) { rows[i] = ty * 4 + i; rows[i + 4] = 64 + ty * 4 + i; }
#pragma unroll
    for (int j = 0; j < 4; j++) { cols[j] = tx * 4 + j; cols[j + 4] = 64 + tx * 4 + j; }
    float bv[8];
#pragma unroll
    for (int j = 0; j < 8; j++) bv[j] = bias[n0 + cols[j]];

    float* outbase = g_xproj + (((size_t)s * GG + g) * BB) * HH + n0;
#pragma unroll
    for (int i = 0; i < 8; i++) {
        float* orow = outbase + (size_t)rows[i] * HH;
#pragma unroll
        for (int j = 0; j < 8; j++) orow[cols[j]] = acc[i][j] + bv[j];
    }
}

// ---------------------------------------------------------------------------
// Kernel 3 (per step): part[ks][g][b][k] = sum_{h in half ks} hm[g,b,h]*U[g][k,h]
// grid = (H/32, G, 2) = 128 CTAs, 256 threads. CTA: M=128 x N=32 x K=256.
// ---------------------------------------------------------------------------
__global__ __launch_bounds__(256) void k_rgemm(Ptrs P) {
    int k0 = blockIdx.x * 32;
    int g  = blockIdx.y;
    int ks = blockIdx.z;
    int hbase = ks * 256;
    const float* __restrict__ U = P.U[g];

    __shared__ float As[16][132];
    __shared__ float Bs[16][36];

    int tid = threadIdx.x;
    int tx = tid & 7, ty = tid >> 3;   // tx: 0..7 (cols*4), ty: 0..31 (rows*4)
    int arow = tid >> 1;               // 0..127
    int acol = (tid & 1) * 8;          // 0 or 8
    int brow = tid >> 3;               // 0..31
    int bcol = (tid & 7) * 2;          // 0..14

    const float* hmrow = g_hm + ((size_t)g * BB + arow) * HH + hbase;
    const float* urow  = U + (size_t)(k0 + brow) * HH + hbase;

    float acc[4][4];
#pragma unroll
    for (int i = 0; i < 4; i++)
#pragma unroll
        for (int j = 0; j < 4; j++) acc[i][j] = 0.0f;

    for (int h0 = 0; h0 < 256; h0 += 16) {
        float4 a0 = *(const float4*)(hmrow + h0 + acol);
        float4 a1 = *(const float4*)(hmrow + h0 + acol + 4);
        float2 b0 = *(const float2*)(urow + h0 + bcol);
        As[acol + 0][arow] = a0.x;
        As[acol + 1][arow] = a0.y;
        As[acol + 2][arow] = a0.z;
        As[acol + 3][arow] = a0.w;
        As[acol + 4][arow] = a1.x;
        As[acol + 5][arow] = a1.y;
        As[acol + 6][arow] = a1.z;
        As[acol + 7][arow] = a1.w;
        Bs[bcol + 0][brow] = b0.x;
        Bs[bcol + 1][brow] = b0.y;
        __syncthreads();
#pragma unroll
        for (int kc = 0; kc < 16; kc++) {
            float4 a = *(const float4*)&As[kc][ty * 4];
            float4 b = *(const float4*)&Bs[kc][tx * 4];
            acc[0][0] += a.x * b.x; acc[0][1] += a.x * b.y; acc[0][2] += a.x * b.z; acc[0][3] += a.x * b.w;
            acc[1][0] += a.y * b.x; acc[1][1] += a.y * b.y; acc[1][2] += a.y * b.z; acc[1][3] += a.y * b.w;
            acc[2][0] += a.z * b.x; acc[2][1] += a.z * b.y; acc[2][2] += a.z * b.z; acc[2][3] += a.z * b.w;
            acc[3][0] += a.w * b.x; acc[3][1] += a.w * b.y; acc[3][2] += a.w * b.z; acc[3][3] += a.w * b.w;
        }
        __syncthreads();
    }

    float* outp = g_part + (((size_t)ks * GG + g) * BB) * HH + k0;
#pragma unroll
    for (int i = 0; i < 4; i++) {
        float* orow = outp + (size_t)(ty * 4 + i) * HH;
#pragma unroll
        for (int j = 0; j < 4; j++) orow[tx * 4 + j] = acc[i][j];
    }
}

// ---------------------------------------------------------------------------
// Kernel 4 (per step): gate nonlinearities + cell update + next-step hm
// ---------------------------------------------------------------------------
__global__ void k_update(int s, Ptrs P, float* __restrict__ out) {
    int idx = blockIdx.x * blockDim.x + threadIdx.x;  // 0..B*H-1
    int b = idx >> 9;      // /512
    int k = idx & 511;

    float pre[4];
#pragma unroll
    for (int g = 0; g < 4; g++) {
        pre[g] = g_part[((size_t)g * BB + b) * HH + k]
               + g_part[(((size_t)4 + g) * BB + b) * HH + k]
               + P.bu[g][k]
               + g_xproj[(((size_t)s * GG + g) * BB + b) * HH + k];
    }
    float ig = sigf(pre[0]);
    float fg = sigf(pre[1]);
    float og = sigf(pre[2]);
    float gg = tanhf(pre[3]);
    float c = fg * g_c[idx] + ig * gg;
    float h = og * tanhf(c);
    g_c[idx] = c;

    out[(size_t)s * BB * HH + idx] = h;  // hn[s]
    if (s == SS - 1) {
        out[(size_t)SS * BB * HH + idx] = h;                  // h_t
        out[(size_t)SS * BB * HH + (size_t)BB * HH + idx] = c; // c_t
    }
#pragma unroll
    for (int g = 0; g < 4; g++)
        g_hm[((size_t)g * BB + b) * HH + k] = h * g_zh[((size_t)g * BB + b) * HH + k];
}

// ---------------------------------------------------------------------------
extern "C" void kernel_launch(void* const* d_in, const int* in_sizes, int n_in,
                              void* d_out, int out_size) {
    const float* x       = (const float*)d_in[0];
    const float* p_logit = (const float*)d_in[1];
    Ptrs P;
    for (int g = 0; g < 4; g++) {
        P.W[g]  = (const float*)d_in[2 + 2 * g];
        P.bx[g] = (const float*)d_in[3 + 2 * g];
        P.U[g]  = (const float*)d_in[10 + 2 * g];
        P.bu[g] = (const float*)d_in[11 + 2 * g];
    }
    const float* ux = (const float*)d_in[18];
    const float* uh = (const float*)d_in[19];
    float* out = (float*)d_out;

    k_setup<<<256, 256>>>(p_logit, ux, uh);
    k_xproj<<<dim3(SS, HH / 128, GG), 256>>>(x, P);
    for (int s = 0; s < SS; s++) {
        k_rgemm<<<dim3(HH / 32, GG, 2), 256>>>(P);
        k_update<<<dim3(BB * HH / 256), 256>>>(s, P, out);
    }
}

// round 5
// speedup vs baseline: 1.1761x; 1.1761x over previous
#include <cuda_runtime.h>
#include <math.h>

#define SS 256
#define BB 128
#define II 256
#define HH 512
#define GG 4
#define EPSF 1e-7f
#define NCTA 128
#define KC 16

struct Ptrs {
    const float* W[4];   // (H,I) input-projection weights, gate order i,f,o,g
    const float* bx[4];  // (H,) input-projection biases
    const float* U[4];   // (H,H) recurrent weights
    const float* bu[4];  // (H,) recurrent biases
};

// Scratch (static device globals: allocation-free at launch time)
__device__ float g_zx[GG * BB * II];                     // 512 KB
__device__ float g_hm[GG * BB * HH];                     // 1 MB  (h * zh per gate)
__device__ float g_part[2 * GG * BB * HH];               // 2 MB  (split-K partials)
__device__ float g_xproj[(size_t)SS * GG * BB * HH];     // 256 MB
__device__ unsigned g_cnt;
__device__ unsigned g_gen;

__device__ __forceinline__ float sigf(float x) { return 1.0f / (1.0f + expf(-x)); }

// ---------------------------------------------------------------------------
// Kernel 1: zx masks + reset grid-barrier state (runs every replay)
// ---------------------------------------------------------------------------
__global__ void k_setup(const float* __restrict__ p_logit,
                        const float* __restrict__ ux) {
    int i = blockIdx.x * blockDim.x + threadIdx.x;
    if (i == 0) { g_cnt = 0u; g_gen = 0u; }
    if (i < GG * BB * II) {
        float p = sigf(p_logit[0]);
        float lp = logf(p + EPSF) - logf(1.0f - p + EPSF);
        float inv = 1.0f / (1.0f - p);
        float u = ux[i];
        float s = sigf((lp + logf(u + EPSF) - logf(1.0f - u + EPSF)) * 10.0f);
        g_zx[i] = (1.0f - s) * inv;
    }
}

// ---------------------------------------------------------------------------
// Kernel 2: xproj[s,g,b,h] = sum_i x[s,b,i]*zx[g,b,i]*W[g][h,i] + bx[g][h]
// grid = (S, H/128, G), 256 threads, 128x128 tile, 8x8 microtile.
// ---------------------------------------------------------------------------
__global__ __launch_bounds__(256) void k_xproj(const float* __restrict__ x, Ptrs P) {
    int s  = blockIdx.x;
    int n0 = blockIdx.y * 128;
    int g  = blockIdx.z;
    const float* __restrict__ W = P.W[g];

    __shared__ float As[8][132];
    __shared__ float Bs[8][132];

    int tid = threadIdx.x;
    int tx = tid & 15, ty = tid >> 4;
    int lrow = tid >> 1;
    int lcol = (tid & 1) * 4;

    const float* xrow = x + ((size_t)s * BB + lrow) * II;
    const float* zrow = g_zx + ((size_t)g * BB + lrow) * II;
    const float* wrow = W + (size_t)(n0 + lrow) * II;

    float acc[8][8];
#pragma unroll
    for (int i = 0; i < 8; i++)
#pragma unroll
        for (int j = 0; j < 8; j++) acc[i][j] = 0.0f;

    for (int i0 = 0; i0 < II; i0 += 8) {
        float4 xa = *(const float4*)(xrow + i0 + lcol);
        float4 za = *(const float4*)(zrow + i0 + lcol);
        float4 wb = *(const float4*)(wrow + i0 + lcol);
        As[lcol + 0][lrow] = xa.x * za.x;
        As[lcol + 1][lrow] = xa.y * za.y;
        As[lcol + 2][lrow] = xa.z * za.z;
        As[lcol + 3][lrow] = xa.w * za.w;
        Bs[lcol + 0][lrow] = wb.x;
        Bs[lcol + 1][lrow] = wb.y;
        Bs[lcol + 2][lrow] = wb.z;
        Bs[lcol + 3][lrow] = wb.w;
        __syncthreads();
#pragma unroll
        for (int kc = 0; kc < 8; kc++) {
            float4 a0 = *(const float4*)&As[kc][ty * 4];
            float4 a1 = *(const float4*)&As[kc][64 + ty * 4];
            float4 b0 = *(const float4*)&Bs[kc][tx * 4];
            float4 b1 = *(const float4*)&Bs[kc][64 + tx * 4];
            float a[8] = {a0.x, a0.y, a0.z, a0.w, a1.x, a1.y, a1.z, a1.w};
            float b[8] = {b0.x, b0.y, b0.z, b0.w, b1.x, b1.y, b1.z, b1.w};
#pragma unroll
            for (int i = 0; i < 8; i++)
#pragma unroll
                for (int j = 0; j < 8; j++) acc[i][j] += a[i] * b[j];
        }
        __syncthreads();
    }

    const float* bias = P.bx[g];
    int rows[8], cols[8];
#pragma unroll
    for (int i = 0; i < 4; i++) { rows[i] = ty * 4 + i; rows[i + 4] = 64 + ty * 4 + i; }
#pragma unroll
    for (int j = 0; j < 4; j++) { cols[j] = tx * 4 + j; cols[j + 4] = 64 + tx * 4 + j; }
    float bv[8];
#pragma unroll
    for (int j = 0; j < 8; j++) bv[j] = bias[n0 + cols[j]];

    float* outbase = g_xproj + (((size_t)s * GG + g) * BB) * HH + n0;
#pragma unroll
    for (int i = 0; i < 8; i++) {
        float* orow = outbase + (size_t)rows[i] * HH;
#pragma unroll
        for (int j = 0; j < 8; j++) orow[cols[j]] = acc[i][j] + bv[j];
    }
}

// ---------------------------------------------------------------------------
// Grid barrier (sense via monotonically increasing generation)
// ---------------------------------------------------------------------------
__device__ __forceinline__ void gbar(unsigned target) {
    __syncthreads();
    if (threadIdx.x == 0) {
        __threadfence();
        unsigned a = atomicAdd(&g_cnt, 1u);
        if (a == NCTA - 1u) {
            g_cnt = 0u;
            __threadfence();
            atomicExch(&g_gen, target);
        } else {
            while (*((volatile unsigned*)&g_gen) < target) __nanosleep(40);
            __threadfence();
        }
    }
    __syncthreads();
}

// ---------------------------------------------------------------------------
// Kernel 3: persistent recurrence. 128 CTAs x 256 threads.
// Phase 1 (GEMM): CTA (g, k0..k0+15) computes pre-activations, U slice in SMEM
//                 (loaded once), split-K=2 across thread halves, 4x4 microtile.
// Phase 2 (update): CTA b==blockIdx.x owns one batch row; c/zh/bu in registers.
// ---------------------------------------------------------------------------
__global__ __launch_bounds__(256, 1) void k_recur(Ptrs P,
        const float* __restrict__ p_logit, const float* __restrict__ uh,
        float* __restrict__ out) {
    extern __shared__ float smf[];
    float (*Us)[16] = (float(*)[16])smf;                       // [512][16]
    float (*As)[KC][132] = (float(*)[KC][132])(smf + 512 * 16); // [4][KC][132]: idx = half*2+buf

    const int tid = threadIdx.x;
    const int cta = blockIdx.x;
    const int gemm_g = cta >> 5;
    const int k0 = (cta & 31) << 4;
    const int half = tid >> 7;
    const int th = tid & 127;
    const int tx = th & 3;           // col-group (x4)
    const int ty = th >> 2;          // row-group (x4)
    const int r0 = th >> 2;          // staging row base
    const int q  = th & 3;           // staging quad
    const int khalf = half << 8;

    // Persistent U slice: Us[i][col] = U[gate][k0+col][i]
    {
        const float* __restrict__ U = P.U[gemm_g];
        for (int idx = tid; idx < 16 * 512; idx += 256) {
            int col = idx >> 9, i = idx & 511;
            Us[i][col] = U[(size_t)(k0 + col) * HH + i];
        }
    }

    // Update-phase per-thread constants (held in registers all 256 steps)
    const int ub = cta;
    const int uk = tid << 1;
    float zh_r[GG][2], bu_r[GG][2];
    {
        float p = sigf(p_logit[0]);
        float lp = logf(p + EPSF) - logf(1.0f - p + EPSF);
        float inv = 1.0f / (1.0f - p);
#pragma unroll
        for (int g = 0; g < GG; g++) {
#pragma unroll
            for (int j = 0; j < 2; j++) {
                float u = uh[((size_t)g * BB + ub) * HH + uk + j];
                float sgm = sigf((lp + logf(u + EPSF) - logf(1.0f - u + EPSF)) * 10.0f);
                zh_r[g][j] = (1.0f - sgm) * inv;
                bu_r[g][j] = P.bu[g][uk + j];
            }
            *(float2*)&g_hm[((size_t)g * BB + ub) * HH + uk] = make_float2(0.f, 0.f);  // h0=0
        }
    }
    float c0 = 0.0f, c1 = 0.0f;

    __syncthreads();          // Us ready (CTA-local)
    unsigned bt = 0;
    gbar(++bt);               // all hm zeros visible chip-wide

    const float* __restrict__ hmb = g_hm + ((size_t)gemm_g * BB) * HH + khalf;
    float* __restrict__ partp = g_part + (((size_t)half * GG + gemm_g) * BB) * HH + k0;

    for (int s = 0; s < SS; s++) {
        // prefetch xproj for this CTA's update elements (hides DRAM latency under GEMM)
        float2 xp[GG];
#pragma unroll
        for (int g = 0; g < GG; g++)
            xp[g] = *(const float2*)&g_xproj[(((size_t)s * GG + g) * BB + ub) * HH + uk];

        // ---------------- Phase 1: GEMM pre[g][b][k0..k0+15] ----------------
        float acc[4][4];
#pragma unroll
        for (int i = 0; i < 4; i++)
#pragma unroll
            for (int j = 0; j < 4; j++) acc[i][j] = 0.0f;

        // stage chunk 0
        {
            float (*Ab)[132] = As[half * 2 + 0];
#pragma unroll
            for (int c2 = 0; c2 < 4; c2++) {
                int r = c2 * 32 + r0;
                float4 v = *(const float4*)(hmb + (size_t)r * HH + q * 4);
                Ab[q * 4 + 0][r] = v.x;
                Ab[q * 4 + 1][r] = v.y;
                Ab[q * 4 + 2][r] = v.z;
                Ab[q * 4 + 3][r] = v.w;
            }
        }
        __syncthreads();

        for (int kb = 0; kb < 16; kb++) {
            int buf = kb & 1;
            float4 st4[4];
            if (kb < 15) {
#pragma unroll
                for (int c2 = 0; c2 < 4; c2++) {
                    int r = c2 * 32 + r0;
                    st4[c2] = *(const float4*)(hmb + (size_t)r * HH + (kb + 1) * KC + q * 4);
                }
            }
            const float (*Ab)[132] = As[half * 2 + buf];
#pragma unroll
            for (int kc = 0; kc < KC; kc++) {
                float4 a = *(const float4*)&Ab[kc][ty * 4];
                float4 w = *(const float4*)&Us[khalf + kb * KC + kc][tx * 4];
                acc[0][0] += a.x * w.x; acc[0][1] += a.x * w.y; acc[0][2] += a.x * w.z; acc[0][3] += a.x * w.w;
                acc[1][0] += a.y * w.x; acc[1][1] += a.y * w.y; acc[1][2] += a.y * w.z; acc[1][3] += a.y * w.w;
                acc[2][0] += a.z * w.x; acc[2][1] += a.z * w.y; acc[2][2] += a.z * w.z; acc[2][3] += a.z * w.w;
                acc[3][0] += a.w * w.x; acc[3][1] += a.w * w.y; acc[3][2] += a.w * w.z; acc[3][3] += a.w * w.w;
            }
            if (kb < 15) {
                float (*An)[132] = As[half * 2 + (buf ^ 1)];
#pragma unroll
                for (int c2 = 0; c2 < 4; c2++) {
                    int r = c2 * 32 + r0;
                    An[q * 4 + 0][r] = st4[c2].x;
                    An[q * 4 + 1][r] = st4[c2].y;
                    An[q * 4 + 2][r] = st4[c2].z;
                    An[q * 4 + 3][r] = st4[c2].w;
                }
            }
            __syncthreads();
        }

        // store split-K partials
#pragma unroll
        for (int i = 0; i < 4; i++) {
            *(float4*)&partp[(size_t)(ty * 4 + i) * HH + tx * 4] =
                make_float4(acc[i][0], acc[i][1], acc[i][2], acc[i][3]);
        }

        gbar(++bt);   // all partials visible

        // ---------------- Phase 2: gate update for batch row ub -------------
        float h0, h1;
        {
            float pre[GG][2];
#pragma unroll
            for (int g = 0; g < GG; g++) {
                float2 pa = *(const float2*)&g_part[(((size_t)0 * GG + g) * BB + ub) * HH + uk];
                float2 pb = *(const float2*)&g_part[(((size_t)1 * GG + g) * BB + ub) * HH + uk];
                pre[g][0] = pa.x + pb.x + bu_r[g][0] + xp[g].x;
                pre[g][1] = pa.y + pb.y + bu_r[g][1] + xp[g].y;
            }
            float i0 = sigf(pre[0][0]), i1 = sigf(pre[0][1]);
            float f0 = sigf(pre[1][0]), f1 = sigf(pre[1][1]);
            float o0 = sigf(pre[2][0]), o1 = sigf(pre[2][1]);
            float gg0 = tanhf(pre[3][0]), gg1 = tanhf(pre[3][1]);
            c0 = f0 * c0 + i0 * gg0;
            c1 = f1 * c1 + i1 * gg1;
            h0 = o0 * tanhf(c0);
            h1 = o1 * tanhf(c1);
        }
        *(float2*)&out[(size_t)s * BB * HH + (size_t)ub * HH + uk] = make_float2(h0, h1);
        if (s == SS - 1) {
            *(float2*)&out[(size_t)SS * BB * HH + (size_t)ub * HH + uk] = make_float2(h0, h1);
            *(float2*)&out[(size_t)(SS + 1) * BB * HH + (size_t)ub * HH + uk] = make_float2(c0, c1);
        }
#pragma unroll
        for (int g = 0; g < GG; g++)
            *(float2*)&g_hm[((size_t)g * BB + ub) * HH + uk] =
                make_float2(h0 * zh_r[g][0], h1 * zh_r[g][1]);

        gbar(++bt);   // hm ready for next step
    }
}

// ---------------------------------------------------------------------------
extern "C" void kernel_launch(void* const* d_in, const int* in_sizes, int n_in,
                              void* d_out, int out_size) {
    const float* x       = (const float*)d_in[0];
    const float* p_logit = (const float*)d_in[1];
    Ptrs P;
    for (int g = 0; g < 4; g++) {
        P.W[g]  = (const float*)d_in[2 + 2 * g];
        P.bx[g] = (const float*)d_in[3 + 2 * g];
        P.U[g]  = (const float*)d_in[10 + 2 * g];
        P.bu[g] = (const float*)d_in[11 + 2 * g];
    }
    const float* ux = (const float*)d_in[18];
    const float* uh = (const float*)d_in[19];
    float* out = (float*)d_out;

    const int SMEM_RECUR = (512 * 16 + 4 * KC * 132) * 4;  // 66560 B
    cudaFuncSetAttribute(k_recur, cudaFuncAttributeMaxDynamicSharedMemorySize, SMEM_RECUR);

    k_setup<<<(GG * BB * II + 255) / 256, 256>>>(p_logit, ux);
    k_xproj<<<dim3(SS, HH / 128, GG), 256>>>(x, P);
    k_recur<<<NCTA, 256, SMEM_RECUR>>>(P, p_logit, uh, out);
}

// round 7
// speedup vs baseline: 1.5763x; 1.3403x over previous
#include <cuda_runtime.h>
#include <cuda_bf16.h>
#include <math.h>

#define SS 256
#define BB 128
#define II 256
#define HH 512
#define GG 4
#define EPSF 1e-7f
#define NCTA 128

struct Ptrs {
    const float* W[4];   // (H,I) input-projection weights, gate order i,f,o,g
    const float* bx[4];  // (H,) input-projection biases
    const float* U[4];   // (H,H) recurrent weights
    const float* bu[4];  // (H,) recurrent biases
};

// Scratch (static device globals: allocation-free at launch time)
__device__ float g_zx[GG * BB * II];                     // 512 KB
__device__ uint2 g_hmA[GG * 256 * BB];                   // 1 MB: A-fragment words (hi-pair, lo-pair)
__device__ float g_part[2 * GG * BB * HH];               // 2 MB  (split-K partials)
__device__ float g_xproj[(size_t)SS * GG * BB * HH];     // 256 MB
__device__ unsigned g_cnt;
__device__ unsigned g_gen;

__device__ __forceinline__ float sigf(float x) { return 1.0f / (1.0f + expf(-x)); }

// pack two floats into (bf16-hi pair, bf16-lo pair)
__device__ __forceinline__ unsigned pk2(float a, float b) {
    return (unsigned)__bfloat16_as_ushort(__float2bfloat16_rn(a)) |
           ((unsigned)__bfloat16_as_ushort(__float2bfloat16_rn(b)) << 16);
}
__device__ __forceinline__ uint2 hilo(float a, float b) {
    __nv_bfloat16 ha = __float2bfloat16_rn(a);
    __nv_bfloat16 hb = __float2bfloat16_rn(b);
    unsigned hi = (unsigned)__bfloat16_as_ushort(ha) |
                  ((unsigned)__bfloat16_as_ushort(hb) << 16);
    float ra = a - __bfloat162float(ha);
    float rb = b - __bfloat162float(hb);
    return make_uint2(hi, pk2(ra, rb));
}

__device__ __forceinline__ void mma16816(float* c,
        unsigned a0, unsigned a1, unsigned a2, unsigned a3,
        unsigned b0, unsigned b1) {
    asm volatile(
        "mma.sync.aligned.m16n8k16.row.col.f32.bf16.bf16.f32 "
        "{%0,%1,%2,%3}, {%4,%5,%6,%7}, {%8,%9}, {%0,%1,%2,%3};"
        : "+f"(c[0]), "+f"(c[1]), "+f"(c[2]), "+f"(c[3])
        : "r"(a0), "r"(a1), "r"(a2), "r"(a3), "r"(b0), "r"(b1));
}

// ---------------------------------------------------------------------------
// Kernel 1: zx masks + reset grid-barrier state (runs every replay)
// ---------------------------------------------------------------------------
__global__ void k_setup(const float* __restrict__ p_logit,
                        const float* __restrict__ ux) {
    int i = blockIdx.x * blockDim.x + threadIdx.x;
    if (i == 0) { g_cnt = 0u; g_gen = 0u; }
    if (i < GG * BB * II) {
        float p = sigf(p_logit[0]);
        float lp = logf(p + EPSF) - logf(1.0f - p + EPSF);
        float inv = 1.0f / (1.0f - p);
        float u = ux[i];
        float s = sigf((lp + logf(u + EPSF) - logf(1.0f - u + EPSF)) * 10.0f);
        g_zx[i] = (1.0f - s) * inv;
    }
}

// ---------------------------------------------------------------------------
// Kernel 2: xproj[s,g,b,h] = sum_i x[s,b,i]*zx[g,b,i]*W[g][h,i] + bx[g][h]
// grid = (S, H/128, G), 256 threads, 128x128 tile, 8x8 microtile.
// ---------------------------------------------------------------------------
__global__ __launch_bounds__(256) void k_xproj(const float* __restrict__ x, Ptrs P) {
    int s  = blockIdx.x;
    int n0 = blockIdx.y * 128;
    int g  = blockIdx.z;
    const float* __restrict__ W = P.W[g];

    __shared__ float As[8][132];
    __shared__ float Bs[8][132];

    int tid = threadIdx.x;
    int tx = tid & 15, ty = tid >> 4;
    int lrow = tid >> 1;
    int lcol = (tid & 1) * 4;

    const float* xrow = x + ((size_t)s * BB + lrow) * II;
    const float* zrow = g_zx + ((size_t)g * BB + lrow) * II;
    const float* wrow = W + (size_t)(n0 + lrow) * II;

    float acc[8][8];
#pragma unroll
    for (int i = 0; i < 8; i++)
#pragma unroll
        for (int j = 0; j < 8; j++) acc[i][j] = 0.0f;

    for (int i0 = 0; i0 < II; i0 += 8) {
        float4 xa = *(const float4*)(xrow + i0 + lcol);
        float4 za = *(const float4*)(zrow + i0 + lcol);
        float4 wb = *(const float4*)(wrow + i0 + lcol);
        As[lcol + 0][lrow] = xa.x * za.x;
        As[lcol + 1][lrow] = xa.y * za.y;
        As[lcol + 2][lrow] = xa.z * za.z;
        As[lcol + 3][lrow] = xa.w * za.w;
        Bs[lcol + 0][lrow] = wb.x;
        Bs[lcol + 1][lrow] = wb.y;
        Bs[lcol + 2][lrow] = wb.z;
        Bs[lcol + 3][lrow] = wb.w;
        __syncthreads();
#pragma unroll
        for (int kc = 0; kc < 8; kc++) {
            float4 a0 = *(const float4*)&As[kc][ty * 4];
            float4 a1 = *(const float4*)&As[kc][64 + ty * 4];
            float4 b0 = *(const float4*)&Bs[kc][tx * 4];
            float4 b1 = *(const float4*)&Bs[kc][64 + tx * 4];
            float a[8] = {a0.x, a0.y, a0.z, a0.w, a1.x, a1.y, a1.z, a1.w};
            float b[8] = {b0.x, b0.y, b0.z, b0.w, b1.x, b1.y, b1.z, b1.w};
#pragma unroll
            for (int i = 0; i < 8; i++)
#pragma unroll
                for (int j = 0; j < 8; j++) acc[i][j] += a[i] * b[j];
        }
        __syncthreads();
    }

    const float* bias = P.bx[g];
    int rows[8], cols[8];
#pragma unroll
    for (int i = 0; i < 4; i++) { rows[i] = ty * 4 + i; rows[i + 4] = 64 + ty * 4 + i; }
#pragma unroll
    for (int j = 0; j < 4; j++) { cols[j] = tx * 4 + j; cols[j + 4] = 64 + tx * 4 + j; }
    float bv[8];
#pragma unroll
    for (int j = 0; j < 8; j++) bv[j] = bias[n0 + cols[j]];

    float* outbase = g_xproj + (((size_t)s * GG + g) * BB) * HH + n0;
#pragma unroll
    for (int i = 0; i < 8; i++) {
        float* orow = outbase + (size_t)rows[i] * HH;
#pragma unroll
        for (int j = 0; j < 8; j++) orow[cols[j]] = acc[i][j] + bv[j];
    }
}

// ---------------------------------------------------------------------------
// Grid barrier (sense via monotonically increasing generation)
// ---------------------------------------------------------------------------
__device__ __forceinline__ void gbar(unsigned target) {
    __syncthreads();
    if (threadIdx.x == 0) {
        __threadfence();
        unsigned a = atomicAdd(&g_cnt, 1u);
        if (a == NCTA - 1u) {
            g_cnt = 0u;
            __threadfence();
            atomicExch(&g_gen, target);
        } else {
            while (*((volatile unsigned*)&g_gen) < target) __nanosleep(32);
            __threadfence();
        }
    }
    __syncthreads();
}

// ---------------------------------------------------------------------------
// Kernel 3: persistent recurrence, bf16x3 tensor-core GEMM.
// 128 CTAs x 256 threads. CTA (g = cta>>5, k0 = (cta&31)*16):
//   Phase 1: pre[128 b][16 k] for gate g, split-K over thread halves (h 0..255 /
//            256..511), mma.sync m16n8k16 with hi/lo bf16 split (3 passes).
//            U slice packed ONCE in SMEM in B-fragment order; A fragments read
//            straight from g_hmA (L2) in fragment-word layout.
//   Phase 2: CTA b==blockIdx.x owns one batch row; c/zh/bu in registers;
//            writes next hm directly as packed A-fragment words.
// ---------------------------------------------------------------------------
__global__ __launch_bounds__(256, 1) void k_recur(Ptrs P,
        const float* __restrict__ p_logit, const float* __restrict__ uh,
        float* __restrict__ out) {
    __shared__ uint2 Wsm[2 * 16 * 4 * 32];   // [half][kk][slot][lane], 32 KB

    const int tid = threadIdx.x;
    const int cta = blockIdx.x;
    const int gemm_g = cta >> 5;
    const int k0 = (cta & 31) << 4;
    const int w = tid >> 5, lane = tid & 31;
    const int half = w >> 2, wm = w & 3;
    const int t = lane & 3, gq = lane >> 2;
    const int R = wm * 32;

    // ---- pack persistent U slice into B-fragment order (hi/lo) ----
    {
        const float* __restrict__ U = P.U[gemm_g];
        for (int idx = tid; idx < 4096; idx += 256) {
            int l   = idx & 31;
            int slt = (idx >> 5) & 3;
            int kk  = (idx >> 7) & 15;
            int hf  = idx >> 11;
            int reg = slt & 1, nt = slt >> 1;
            int h   = hf * 256 + kk * 16 + reg * 8 + (l & 3) * 2;
            int col = k0 + nt * 8 + (l >> 2);
            float u0 = U[(size_t)col * HH + h];
            float u1 = U[(size_t)col * HH + h + 1];
            Wsm[idx] = hilo(u0, u1);
        }
    }

    // ---- update-phase constants (registers, all 256 steps) ----
    const int ub = cta;
    const int uk = tid << 1;
    float zh_r[GG][2], bu_r[GG][2];
    {
        float p = sigf(p_logit[0]);
        float lp = logf(p + EPSF) - logf(1.0f - p + EPSF);
        float inv = 1.0f / (1.0f - p);
#pragma unroll
        for (int g = 0; g < GG; g++) {
#pragma unroll
            for (int j = 0; j < 2; j++) {
                float u = uh[((size_t)g * BB + ub) * HH + uk + j];
                float sgm = sigf((lp + logf(u + EPSF) - logf(1.0f - u + EPSF)) * 10.0f);
                zh_r[g][j] = (1.0f - sgm) * inv;
                bu_r[g][j] = P.bu[g][uk + j];
            }
            g_hmA[((size_t)g * 256 + tid) * BB + ub] = make_uint2(0u, 0u);  // h0 = 0
        }
    }
    float c0 = 0.0f, c1 = 0.0f;

    __syncthreads();
    unsigned bt = 0;
    gbar(++bt);   // hm zeros visible chip-wide

    // A-fragment base: index(h2, b) = h2*128 + b; h2 = half*128 + kk*8 + t (+4)
    const uint2* __restrict__ Abase =
        g_hmA + (size_t)gemm_g * (256 * BB) + ((size_t)(half * 128 + t)) * BB + R + gq;
    float* __restrict__ partp =
        g_part + (((size_t)half * GG + gemm_g) * BB) * HH + k0;

    for (int s = 0; s < SS; s++) {
        // prefetch xproj for this CTA's update elements
        float2 xp[GG];
#pragma unroll
        for (int g = 0; g < GG; g++)
            xp[g] = *(const float2*)&g_xproj[(((size_t)s * GG + g) * BB + ub) * HH + uk];

        // ---------------- Phase 1: bf16x3 MMA GEMM ----------------
        float acc[2][2][4];
#pragma unroll
        for (int mt = 0; mt < 2; mt++)
#pragma unroll
            for (int nt = 0; nt < 2; nt++)
#pragma unroll
                for (int i = 0; i < 4; i++) acc[mt][nt][i] = 0.0f;

        uint2 Ab[3][8];   // 3-stage pipeline, [mt*4 + reg]
#pragma unroll
        for (int pf = 0; pf < 2; pf++) {
            const uint2* p = Abase + (size_t)pf * 1024;
#pragma unroll
            for (int mt = 0; mt < 2; mt++) {
                const uint2* q = p + mt * 16;
                Ab[pf][mt * 4 + 0] = __ldcg(q);
                Ab[pf][mt * 4 + 1] = __ldcg(q + 8);
                Ab[pf][mt * 4 + 2] = __ldcg(q + 512);
                Ab[pf][mt * 4 + 3] = __ldcg(q + 520);
            }
        }

#pragma unroll
        for (int kk = 0; kk < 16; kk++) {
            const int cur = kk % 3;
            const int nxt = (kk + 2) % 3;
            if (kk < 14) {
                const uint2* p = Abase + (size_t)(kk + 2) * 1024;
#pragma unroll
                for (int mt = 0; mt < 2; mt++) {
                    const uint2* q = p + mt * 16;
                    Ab[nxt][mt * 4 + 0] = __ldcg(q);
                    Ab[nxt][mt * 4 + 1] = __ldcg(q + 8);
                    Ab[nxt][mt * 4 + 2] = __ldcg(q + 512);
                    Ab[nxt][mt * 4 + 3] = __ldcg(q + 520);
                }
            }
            const uint2* Wp = &Wsm[((half * 16 + kk) * 4) * 32 + lane];
#pragma unroll
            for (int nt = 0; nt < 2; nt++) {
                uint2 wb0 = Wp[(nt * 2 + 0) * 32];
                uint2 wb1 = Wp[(nt * 2 + 1) * 32];
#pragma unroll
                for (int mt = 0; mt < 2; mt++) {
                    unsigned ah0 = Ab[cur][mt * 4 + 0].x, al0 = Ab[cur][mt * 4 + 0].y;
                    unsigned ah1 = Ab[cur][mt * 4 + 1].x, al1 = Ab[cur][mt * 4 + 1].y;
                    unsigned ah2 = Ab[cur][mt * 4 + 2].x, al2 = Ab[cur][mt * 4 + 2].y;
                    unsigned ah3 = Ab[cur][mt * 4 + 3].x, al3 = Ab[cur][mt * 4 + 3].y;
                    mma16816(acc[mt][nt], ah0, ah1, ah2, ah3, wb0.x, wb1.x);  // hi*hi
                    mma16816(acc[mt][nt], ah0, ah1, ah2, ah3, wb0.y, wb1.y);  // hi*lo
                    mma16816(acc[mt][nt], al0, al1, al2, al3, wb0.x, wb1.x);  // lo*hi
                }
            }
        }

        // store split-K partials
#pragma unroll
        for (int mt = 0; mt < 2; mt++) {
#pragma unroll
            for (int nt = 0; nt < 2; nt++) {
                int r = R + mt * 16 + gq;
                int cb = nt * 8 + t * 2;
                *(float2*)&partp[(size_t)r * HH + cb] =
                    make_float2(acc[mt][nt][0], acc[mt][nt][1]);
                *(float2*)&partp[(size_t)(r + 8) * HH + cb] =
                    make_float2(acc[mt][nt][2], acc[mt][nt][3]);
            }
        }

        gbar(++bt);   // all partials visible

        // ---------------- Phase 2: gate update for batch row ub -------------
        float h0, h1;
        {
            float pre[GG][2];
#pragma unroll
            for (int g = 0; g < GG; g++) {
                float2 pa = __ldcg((const float2*)&g_part[(((size_t)0 * GG + g) * BB + ub) * HH + uk]);
                float2 pb = __ldcg((const float2*)&g_part[(((size_t)1 * GG + g) * BB + ub) * HH + uk]);
                pre[g][0] = pa.x + pb.x + bu_r[g][0] + xp[g].x;
                pre[g][1] = pa.y + pb.y + bu_r[g][1] + xp[g].y;
            }
            float i0 = sigf(pre[0][0]), i1 = sigf(pre[0][1]);
            float f0 = sigf(pre[1][0]), f1 = sigf(pre[1][1]);
            float o0 = sigf(pre[2][0]), o1 = sigf(pre[2][1]);
            float gg0 = tanhf(pre[3][0]), gg1 = tanhf(pre[3][1]);
            c0 = f0 * c0 + i0 * gg0;
            c1 = f1 * c1 + i1 * gg1;
            h0 = o0 * tanhf(c0);
            h1 = o1 * tanhf(c1);
        }
        *(float2*)&out[(size_t)s * BB * HH + (size_t)ub * HH + uk] = make_float2(h0, h1);
        if (s == SS - 1) {
            *(float2*)&out[(size_t)SS * BB * HH + (size_t)ub * HH + uk] = make_float2(h0, h1);
            *(float2*)&out[(size_t)(SS + 1) * BB * HH + (size_t)ub * HH + uk] = make_float2(c0, c1);
        }
#pragma unroll
        for (int g = 0; g < GG; g++)
            g_hmA[((size_t)g * 256 + tid) * BB + ub] =
                hilo(h0 * zh_r[g][0], h1 * zh_r[g][1]);

        gbar(++bt);   // hm ready for next step
    }
}

// ---------------------------------------------------------------------------
extern "C" void kernel_launch(void* const* d_in, const int* in_sizes, int n_in,
                              void* d_out, int out_size) {
    const float* x       = (const float*)d_in[0];
    const float* p_logit = (const float*)d_in[1];
    Ptrs P;
    for (int g = 0; g < 4; g++) {
        P.W[g]  = (const float*)d_in[2 + 2 * g];
        P.bx[g] = (const float*)d_in[3 + 2 * g];
        P.U[g]  = (const float*)d_in[10 + 2 * g];
        P.bu[g] = (const float*)d_in[11 + 2 * g];
    }
    const float* ux = (const float*)d_in[18];
    const float* uh = (const float*)d_in[19];
    float* out = (float*)d_out;

    k_setup<<<(GG * BB * II + 255) / 256, 256>>>(p_logit, ux);
    k_xproj<<<dim3(SS, HH / 128, GG), 256>>>(x, P);
    k_recur<<<NCTA, 256>>>(P, p_logit, uh, out);
}

// round 8
// speedup vs baseline: 1.8136x; 1.1506x over previous
#include <cuda_runtime.h>
#include <cuda_bf16.h>
#include <math.h>

#define SS 256
#define BB 128
#define II 256
#define HH 512
#define GG 4
#define EPSF 1e-7f
#define NCTA 128

struct Ptrs {
    const float* W[4];   // (H,I) input-projection weights, gate order i,f,o,g
    const float* bx[4];  // (H,) input-projection biases
    const float* U[4];   // (H,H) recurrent weights
    const float* bu[4];  // (H,) recurrent biases
};

// Scratch (static device globals: allocation-free at launch time)
__device__ float g_zx[GG * BB * II];                     // 512 KB
__device__ uint2 g_hmA[GG * 256 * BB];                   // 1 MB: A-fragment words (hi,lo)
__device__ uint2 g_WB[GG * 128 * HH];                    // 2 MB: W B-fragment words (hi,lo)
__device__ float g_part[2 * GG * BB * HH];               // 2 MB  (split-K partials)
__device__ float g_xproj[(size_t)SS * GG * BB * HH];     // 256 MB
__device__ unsigned g_cnt;
__device__ unsigned g_gen;

__device__ __forceinline__ float sigf(float x) { return 1.0f / (1.0f + expf(-x)); }

__device__ __forceinline__ unsigned pk2(float a, float b) {
    return (unsigned)__bfloat16_as_ushort(__float2bfloat16_rn(a)) |
           ((unsigned)__bfloat16_as_ushort(__float2bfloat16_rn(b)) << 16);
}
__device__ __forceinline__ uint2 hilo(float a, float b) {
    __nv_bfloat16 ha = __float2bfloat16_rn(a);
    __nv_bfloat16 hb = __float2bfloat16_rn(b);
    unsigned hi = (unsigned)__bfloat16_as_ushort(ha) |
                  ((unsigned)__bfloat16_as_ushort(hb) << 16);
    return make_uint2(hi, pk2(a - __bfloat162float(ha), b - __bfloat162float(hb)));
}

__device__ __forceinline__ void mma16816(float* c,
        unsigned a0, unsigned a1, unsigned a2, unsigned a3,
        unsigned b0, unsigned b1) {
    asm volatile(
        "mma.sync.aligned.m16n8k16.row.col.f32.bf16.bf16.f32 "
        "{%0,%1,%2,%3}, {%4,%5,%6,%7}, {%8,%9}, {%0,%1,%2,%3};"
        : "+f"(c[0]), "+f"(c[1]), "+f"(c[2]), "+f"(c[3])
        : "r"(a0), "r"(a1), "r"(a2), "r"(a3), "r"(b0), "r"(b1));
}

// ---------------------------------------------------------------------------
// Kernel 1: zx masks + reset grid-barrier state (runs every replay)
// ---------------------------------------------------------------------------
__global__ void k_setup(const float* __restrict__ p_logit,
                        const float* __restrict__ ux) {
    int i = blockIdx.x * blockDim.x + threadIdx.x;
    if (i == 0) { g_cnt = 0u; g_gen = 0u; }
    if (i < GG * BB * II) {
        float p = sigf(p_logit[0]);
        float lp = logf(p + EPSF) - logf(1.0f - p + EPSF);
        float inv = 1.0f / (1.0f - p);
        float u = ux[i];
        float s = sigf((lp + logf(u + EPSF) - logf(1.0f - u + EPSF)) * 10.0f);
        g_zx[i] = (1.0f - s) * inv;
    }
}

// ---------------------------------------------------------------------------
// Kernel 1b: pack W into B-fragment hi/lo words: g_WB[(g*128 + k2)*512 + h]
//            = hilo(W[g][h][2*k2], W[g][h][2*k2+1])
// ---------------------------------------------------------------------------
__global__ void k_pack(Ptrs P) {
    int idx = blockIdx.x * blockDim.x + threadIdx.x;   // 0 .. 4*128*512-1
    int g = idx >> 16;
    int r = idx & 65535;
    int k2 = r >> 9;
    int h = r & 511;
    const float* Wg = P.W[g];
    g_WB[idx] = hilo(Wg[h * II + 2 * k2], Wg[h * II + 2 * k2 + 1]);
}

// ---------------------------------------------------------------------------
// Kernel 2: xproj via bf16x3 mma. grid=(S, 4, G), 256 thr.
// CTA tile: M=128(b) x N=128(h) x K=256(i). Warps: wm=w&3 (rows wm*32, 2 mt),
// wn=w>>2 (cols wn*64, 8 nt). A converted on the fly; B from g_WB via smem.
// ---------------------------------------------------------------------------
__global__ __launch_bounds__(256, 1) void k_xproj(const float* __restrict__ x, Ptrs P) {
    __shared__ uint2 Bs[128 * 9];   // [col][k2], stride 9 to break conflicts

    const int s  = blockIdx.x;
    const int nb = blockIdx.y * 128;
    const int g  = blockIdx.z;

    const int tid = threadIdx.x;
    const int w = tid >> 5, lane = tid & 31;
    const int wm = w & 3, wn = w >> 2;
    const int gq = lane >> 2, t = lane & 3;
    const int R = wm * 32;

    const float* __restrict__ xs  = x + (size_t)s * BB * II;
    const float* __restrict__ zxg = g_zx + (size_t)g * BB * II;

    // B staging: thread loads 4 words (col = tid&127, k2 = (tid>>7)*4 + j)
    const int bcol = tid & 127;
    const int bk2  = (tid >> 7) * 4;
    const uint2* __restrict__ WBbase = g_WB + ((size_t)g * 128 + bk2) * 512 + nb + bcol;

    float2 xv[8], zv[8];
    uint2 Aw[8];
    uint2 Bn[4];

    // raw A rows/cols for this thread (8 words: mt*4 + {0..3})
    int arow[8], ak2r[8];
#pragma unroll
    for (int mt = 0; mt < 2; mt++)
#pragma unroll
        for (int wd = 0; wd < 4; wd++) {
            arow[mt * 4 + wd] = R + mt * 16 + gq + (wd & 1) * 8;
            ak2r[mt * 4 + wd] = t + (wd >> 1) * 4;
        }

    // preload chunk 0
#pragma unroll
    for (int q = 0; q < 8; q++) {
        int off = arow[q] * II + 2 * ak2r[q];
        xv[q] = *(const float2*)(xs + off);
        zv[q] = *(const float2*)(zxg + off);
    }
#pragma unroll
    for (int j = 0; j < 4; j++) Bn[j] = __ldcg(WBbase + (size_t)j * 512);
#pragma unroll
    for (int j = 0; j < 4; j++) Bs[bcol * 9 + bk2 + j] = Bn[j];
    __syncthreads();

    float acc[2][8][4];
#pragma unroll
    for (int mt = 0; mt < 2; mt++)
#pragma unroll
        for (int nt = 0; nt < 8; nt++)
#pragma unroll
            for (int i = 0; i < 4; i++) acc[mt][nt][i] = 0.0f;

    for (int kc = 0; kc < 16; kc++) {
        // convert current raw A to hi/lo words
#pragma unroll
        for (int q = 0; q < 8; q++)
            Aw[q] = hilo(xv[q].x * zv[q].x, xv[q].y * zv[q].y);

        // prefetch next chunk (A raw + B words)
        if (kc < 15) {
#pragma unroll
            for (int q = 0; q < 8; q++) {
                int off = arow[q] * II + 2 * ((kc + 1) * 8 + ak2r[q]);
                xv[q] = *(const float2*)(xs + off);
                zv[q] = *(const float2*)(zxg + off);
            }
#pragma unroll
            for (int j = 0; j < 4; j++)
                Bn[j] = __ldcg(WBbase + (size_t)((kc + 1) * 8 + j) * 512);
        }

        // MMA over 8 n-tiles x 2 m-tiles x 3 passes
#pragma unroll
        for (int nt = 0; nt < 8; nt++) {
            int colg = wn * 64 + nt * 8 + gq;
            uint2 b0 = Bs[colg * 9 + t];
            uint2 b1 = Bs[colg * 9 + t + 4];
#pragma unroll
            for (int mt = 0; mt < 2; mt++) {
                unsigned h0 = Aw[mt*4+0].x, h1 = Aw[mt*4+1].x, h2 = Aw[mt*4+2].x, h3 = Aw[mt*4+3].x;
                unsigned l0 = Aw[mt*4+0].y, l1 = Aw[mt*4+1].y, l2 = Aw[mt*4+2].y, l3 = Aw[mt*4+3].y;
                mma16816(acc[mt][nt], h0, h1, h2, h3, b0.x, b1.x);  // hi*hi
                mma16816(acc[mt][nt], h0, h1, h2, h3, b0.y, b1.y);  // hi*lo
                mma16816(acc[mt][nt], l0, l1, l2, l3, b0.x, b1.x);  // lo*hi
            }
        }

        if (kc < 15) {
            __syncthreads();
#pragma unroll
            for (int j = 0; j < 4; j++) Bs[bcol * 9 + bk2 + j] = Bn[j];
            __syncthreads();
        }
    }

    // epilogue: bias + store fp32
    const float* bias = P.bx[g];
    float* outb = g_xproj + (((size_t)s * GG + g) * BB) * HH + nb;
#pragma unroll
    for (int nt = 0; nt < 8; nt++) {
        int col = wn * 64 + nt * 8 + 2 * t;
        float b0 = bias[nb + col], b1 = bias[nb + col + 1];
#pragma unroll
        for (int mt = 0; mt < 2; mt++) {
            int r = R + mt * 16 + gq;
            *(float2*)(outb + (size_t)r * HH + col) =
                make_float2(acc[mt][nt][0] + b0, acc[mt][nt][1] + b1);
            *(float2*)(outb + (size_t)(r + 8) * HH + col) =
                make_float2(acc[mt][nt][2] + b0, acc[mt][nt][3] + b1);
        }
    }
}

// ---------------------------------------------------------------------------
// Grid barrier
// ---------------------------------------------------------------------------
__device__ __forceinline__ void gbar(unsigned target) {
    __syncthreads();
    if (threadIdx.x == 0) {
        __threadfence();
        unsigned a = atomicAdd(&g_cnt, 1u);
        if (a == NCTA - 1u) {
            g_cnt = 0u;
            __threadfence();
            atomicExch(&g_gen, target);
        } else {
            while (*((volatile unsigned*)&g_gen) < target) __nanosleep(32);
            __threadfence();
        }
    }
    __syncthreads();
}

// ---------------------------------------------------------------------------
// Kernel 3: persistent recurrence, bf16x3 MMA.
// CTA c: gemm_g = c>>5; c5 = c&31: k0 = (c5>>1)*32 (N=32 cols), mbase=(c5&1)*64.
// Warps: wm=w&3 (rows mbase+wm*16), kh=w>>2 (K half of 256). Split-K partials.
// Update phase: CTA b==blockIdx.x owns one batch row (unchanged from R7).
// ---------------------------------------------------------------------------
__global__ __launch_bounds__(256, 1) void k_recur(Ptrs P,
        const float* __restrict__ p_logit, const float* __restrict__ uh,
        float* __restrict__ out) {
    extern __shared__ uint2 Wsm[];   // [kh 2][kk 16][slot 8][lane 32] = 64 KB

    const int tid = threadIdx.x;
    const int cta = blockIdx.x;
    const int gemm_g = cta >> 5;
    const int c5 = cta & 31;
    const int k0 = (c5 >> 1) * 32;
    const int mbase = (c5 & 1) * 64;
    const int w = tid >> 5, lane = tid & 31;
    const int wm = w & 3, kh = w >> 2;
    const int gq = lane >> 2, t = lane & 3;
    const int rbase = mbase + wm * 16;

    // ---- pack persistent U slice into B-fragment order (hi/lo), once ----
    {
        const float* __restrict__ U = P.U[gemm_g];
        for (int idx = tid; idx < 8192; idx += 256) {
            int l   = idx & 31;
            int slt = (idx >> 5) & 7;
            int kkl = (idx >> 8) & 15;
            int hf  = idx >> 12;
            int reg = slt & 1, nt = slt >> 1;
            int h   = hf * 256 + kkl * 16 + reg * 8 + (l & 3) * 2;
            int col = k0 + nt * 8 + (l >> 2);
            Wsm[idx] = hilo(U[(size_t)col * HH + h], U[(size_t)col * HH + h + 1]);
        }
    }

    // ---- update-phase constants (registers, all 256 steps) ----
    const int ub = cta;
    const int uk = tid << 1;
    float zh_r[GG][2], bu_r[GG][2];
    {
        float p = sigf(p_logit[0]);
        float lp = logf(p + EPSF) - logf(1.0f - p + EPSF);
        float inv = 1.0f / (1.0f - p);
#pragma unroll
        for (int g = 0; g < GG; g++) {
#pragma unroll
            for (int j = 0; j < 2; j++) {
                float u = uh[((size_t)g * BB + ub) * HH + uk + j];
                float sgm = sigf((lp + logf(u + EPSF) - logf(1.0f - u + EPSF)) * 10.0f);
                zh_r[g][j] = (1.0f - sgm) * inv;
                bu_r[g][j] = P.bu[g][uk + j];
            }
            g_hmA[((size_t)g * 256 + tid) * BB + ub] = make_uint2(0u, 0u);  // h0 = 0
        }
    }
    float c0 = 0.0f, c1 = 0.0f;

    __syncthreads();
    unsigned bt = 0;
    gbar(++bt);   // hm zeros visible chip-wide

    const uint2* __restrict__ Abase =
        g_hmA + ((size_t)(gemm_g * 256 + kh * 128 + t)) * BB + rbase + gq;
    float* __restrict__ partp =
        g_part + (((size_t)kh * GG + gemm_g) * BB) * HH;

    for (int s = 0; s < SS; s++) {
        // prefetch xproj for this CTA's update elements
        float2 xp[GG];
#pragma unroll
        for (int g = 0; g < GG; g++)
            xp[g] = *(const float2*)&g_xproj[(((size_t)s * GG + g) * BB + ub) * HH + uk];

        // ---------------- Phase 1: bf16x3 MMA GEMM ----------------
        float acc[4][4];
#pragma unroll
        for (int nt = 0; nt < 4; nt++)
#pragma unroll
            for (int i = 0; i < 4; i++) acc[nt][i] = 0.0f;

        uint2 Ab[4][4];   // 4-stage ring
#pragma unroll
        for (int pf = 0; pf < 3; pf++) {
            const uint2* q = Abase + (size_t)pf * 1024;
            Ab[pf][0] = __ldcg(q);
            Ab[pf][1] = __ldcg(q + 8);
            Ab[pf][2] = __ldcg(q + 512);
            Ab[pf][3] = __ldcg(q + 520);
        }

#pragma unroll
        for (int kkl = 0; kkl < 16; kkl++) {
            const int cur = kkl & 3;
            if (kkl < 13) {
                const int nxt = (kkl + 3) & 3;
                const uint2* q = Abase + (size_t)(kkl + 3) * 1024;
                Ab[nxt][0] = __ldcg(q);
                Ab[nxt][1] = __ldcg(q + 8);
                Ab[nxt][2] = __ldcg(q + 512);
                Ab[nxt][3] = __ldcg(q + 520);
            }
            unsigned ah0 = Ab[cur][0].x, ah1 = Ab[cur][1].x, ah2 = Ab[cur][2].x, ah3 = Ab[cur][3].x;
            unsigned al0 = Ab[cur][0].y, al1 = Ab[cur][1].y, al2 = Ab[cur][2].y, al3 = Ab[cur][3].y;
            const uint2* Wp = &Wsm[((kh * 16 + kkl) * 8) * 32 + lane];
#pragma unroll
            for (int nt = 0; nt < 4; nt++) {
                uint2 wb0 = Wp[(nt * 2 + 0) * 32];
                uint2 wb1 = Wp[(nt * 2 + 1) * 32];
                mma16816(acc[nt], ah0, ah1, ah2, ah3, wb0.x, wb1.x);  // hi*hi
                mma16816(acc[nt], ah0, ah1, ah2, ah3, wb0.y, wb1.y);  // hi*lo
                mma16816(acc[nt], al0, al1, al2, al3, wb0.x, wb1.x);  // lo*hi
            }
        }

        // store split-K partials
#pragma unroll
        for (int nt = 0; nt < 4; nt++) {
            int col = k0 + nt * 8 + 2 * t;
            int r = rbase + gq;
            *(float2*)&partp[(size_t)r * HH + col] = make_float2(acc[nt][0], acc[nt][1]);
            *(float2*)&partp[(size_t)(r + 8) * HH + col] = make_float2(acc[nt][2], acc[nt][3]);
        }

        gbar(++bt);   // all partials visible

        // ---------------- Phase 2: gate update for batch row ub -------------
        float h0, h1;
        {
            float pre[GG][2];
#pragma unroll
            for (int g = 0; g < GG; g++) {
                float2 pa = __ldcg((const float2*)&g_part[(((size_t)0 * GG + g) * BB + ub) * HH + uk]);
                float2 pb = __ldcg((const float2*)&g_part[(((size_t)1 * GG + g) * BB + ub) * HH + uk]);
                pre[g][0] = pa.x + pb.x + bu_r[g][0] + xp[g].x;
                pre[g][1] = pa.y + pb.y + bu_r[g][1] + xp[g].y;
            }
            float i0 = sigf(pre[0][0]), i1 = sigf(pre[0][1]);
            float f0 = sigf(pre[1][0]), f1 = sigf(pre[1][1]);
            float o0 = sigf(pre[2][0]), o1 = sigf(pre[2][1]);
            float gg0 = tanhf(pre[3][0]), gg1 = tanhf(pre[3][1]);
            c0 = f0 * c0 + i0 * gg0;
            c1 = f1 * c1 + i1 * gg1;
            h0 = o0 * tanhf(c0);
            h1 = o1 * tanhf(c1);
        }
        *(float2*)&out[(size_t)s * BB * HH + (size_t)ub * HH + uk] = make_float2(h0, h1);
        if (s == SS - 1) {
            *(float2*)&out[(size_t)SS * BB * HH + (size_t)ub * HH + uk] = make_float2(h0, h1);
            *(float2*)&out[(size_t)(SS + 1) * BB * HH + (size_t)ub * HH + uk] = make_float2(c0, c1);
        }
#pragma unroll
        for (int g = 0; g < GG; g++)
            g_hmA[((size_t)g * 256 + tid) * BB + ub] =
                hilo(h0 * zh_r[g][0], h1 * zh_r[g][1]);

        gbar(++bt);   // hm ready for next step
    }
}

// ---------------------------------------------------------------------------
extern "C" void kernel_launch(void* const* d_in, const int* in_sizes, int n_in,
                              void* d_out, int out_size) {
    const float* x       = (const float*)d_in[0];
    const float* p_logit = (const float*)d_in[1];
    Ptrs P;
    for (int g = 0; g < 4; g++) {
        P.W[g]  = (const float*)d_in[2 + 2 * g];
        P.bx[g] = (const float*)d_in[3 + 2 * g];
        P.U[g]  = (const float*)d_in[10 + 2 * g];
        P.bu[g] = (const float*)d_in[11 + 2 * g];
    }
    const float* ux = (const float*)d_in[18];
    const float* uh = (const float*)d_in[19];
    float* out = (float*)d_out;

    const int WSM = 2 * 16 * 8 * 32 * (int)sizeof(uint2);   // 65536 B
    cudaFuncSetAttribute(k_recur, cudaFuncAttributeMaxDynamicSharedMemorySize, WSM);

    k_setup<<<(GG * BB * II + 255) / 256, 256>>>(p_logit, ux);
    k_pack<<<(GG * 128 * HH) / 256, 256>>>(P);
    k_xproj<<<dim3(SS, HH / 128, GG), 256>>>(x, P);
    k_recur<<<NCTA, 256, WSM>>>(P, p_logit, uh, out);
}

// round 9
// speedup vs baseline: 2.0439x; 1.1270x over previous
#include <cuda_runtime.h>
#include <cuda_bf16.h>
#include <math.h>

#define SS 256
#define BB 128
#define II 256
#define HH 512
#define GG 4
#define EPSF 1e-7f
#define NCTA 128

struct Ptrs {
    const float* W[4];   // (H,I) input-projection weights, gate order i,f,o,g
    const float* bx[4];  // (H,) input-projection biases
    const float* U[4];   // (H,H) recurrent weights
    const float* bu[4];  // (H,) recurrent biases
};

// Scratch (static device globals: allocation-free at launch time)
__device__ float g_zx[GG * BB * II];                     // 512 KB
__device__ uint2 g_hmA[GG * 256 * BB];                   // 1 MB: A-fragment words (hi,lo)
__device__ uint2 g_WB[GG * 128 * HH];                    // 2 MB: W B-fragment words (hi,lo)
__device__ float g_xproj[(size_t)SS * GG * BB * HH];     // 256 MB
__device__ unsigned g_cnt;
__device__ unsigned g_gen;

__device__ __forceinline__ float sigf(float x) { return 1.0f / (1.0f + expf(-x)); }

__device__ __forceinline__ unsigned pk2(float a, float b) {
    return (unsigned)__bfloat16_as_ushort(__float2bfloat16_rn(a)) |
           ((unsigned)__bfloat16_as_ushort(__float2bfloat16_rn(b)) << 16);
}
__device__ __forceinline__ uint2 hilo(float a, float b) {
    __nv_bfloat16 ha = __float2bfloat16_rn(a);
    __nv_bfloat16 hb = __float2bfloat16_rn(b);
    unsigned hi = (unsigned)__bfloat16_as_ushort(ha) |
                  ((unsigned)__bfloat16_as_ushort(hb) << 16);
    return make_uint2(hi, pk2(a - __bfloat162float(ha), b - __bfloat162float(hb)));
}

__device__ __forceinline__ void mma16816(float* c,
        unsigned a0, unsigned a1, unsigned a2, unsigned a3,
        unsigned b0, unsigned b1) {
    asm volatile(
        "mma.sync.aligned.m16n8k16.row.col.f32.bf16.bf16.f32 "
        "{%0,%1,%2,%3}, {%4,%5,%6,%7}, {%8,%9}, {%0,%1,%2,%3};"
        : "+f"(c[0]), "+f"(c[1]), "+f"(c[2]), "+f"(c[3])
        : "r"(a0), "r"(a1), "r"(a2), "r"(a3), "r"(b0), "r"(b1));
}

// ---------------------------------------------------------------------------
// Kernel 1: zx masks + reset grid-barrier state (runs every replay)
// ---------------------------------------------------------------------------
__global__ void k_setup(const float* __restrict__ p_logit,
                        const float* __restrict__ ux) {
    int i = blockIdx.x * blockDim.x + threadIdx.x;
    if (i == 0) { g_cnt = 0u; g_gen = 0u; }
    if (i < GG * BB * II) {
        float p = sigf(p_logit[0]);
        float lp = logf(p + EPSF) - logf(1.0f - p + EPSF);
        float inv = 1.0f / (1.0f - p);
        float u = ux[i];
        float s = sigf((lp + logf(u + EPSF) - logf(1.0f - u + EPSF)) * 10.0f);
        g_zx[i] = (1.0f - s) * inv;
    }
}

// ---------------------------------------------------------------------------
// Kernel 1b: pack W into B-fragment hi/lo words
// ---------------------------------------------------------------------------
__global__ void k_pack(Ptrs P) {
    int idx = blockIdx.x * blockDim.x + threadIdx.x;   // 0 .. 4*128*512-1
    int g = idx >> 16;
    int r = idx & 65535;
    int k2 = r >> 9;
    int h = r & 511;
    const float* Wg = P.W[g];
    g_WB[idx] = hilo(Wg[h * II + 2 * k2], Wg[h * II + 2 * k2 + 1]);
}

// ---------------------------------------------------------------------------
// Kernel 2: xproj via bf16x3 mma. grid=(S, 4, G), 256 thr.
// CTA tile: M=128(b) x N=128(h) x K=256(i). Double-buffered B staging.
// ---------------------------------------------------------------------------
__global__ __launch_bounds__(256, 1) void k_xproj(const float* __restrict__ x, Ptrs P) {
    __shared__ uint2 Bs[2][128 * 9];   // [buf][col*9 + k2]

    const int s  = blockIdx.x;
    const int nb = blockIdx.y * 128;
    const int g  = blockIdx.z;

    const int tid = threadIdx.x;
    const int w = tid >> 5, lane = tid & 31;
    const int wm = w & 3, wn = w >> 2;
    const int gq = lane >> 2, t = lane & 3;
    const int R = wm * 32;

    const float* __restrict__ xs  = x + (size_t)s * BB * II;
    const float* __restrict__ zxg = g_zx + (size_t)g * BB * II;

    const int bcol = tid & 127;
    const int bk2  = (tid >> 7) * 4;
    const uint2* __restrict__ WBbase = g_WB + ((size_t)g * 128 + bk2) * 512 + nb + bcol;

    float2 xv[8], zv[8];
    uint2 Aw[8];
    uint2 Bn[4];

    int arow[8], ak2r[8];
#pragma unroll
    for (int mt = 0; mt < 2; mt++)
#pragma unroll
        for (int wd = 0; wd < 4; wd++) {
            arow[mt * 4 + wd] = R + mt * 16 + gq + (wd & 1) * 8;
            ak2r[mt * 4 + wd] = t + (wd >> 1) * 4;
        }

#pragma unroll
    for (int q = 0; q < 8; q++) {
        int off = arow[q] * II + 2 * ak2r[q];
        xv[q] = *(const float2*)(xs + off);
        zv[q] = *(const float2*)(zxg + off);
    }
#pragma unroll
    for (int j = 0; j < 4; j++) Bn[j] = __ldcg(WBbase + (size_t)j * 512);
#pragma unroll
    for (int j = 0; j < 4; j++) Bs[0][bcol * 9 + bk2 + j] = Bn[j];
    __syncthreads();

    float acc[2][8][4];
#pragma unroll
    for (int mt = 0; mt < 2; mt++)
#pragma unroll
        for (int nt = 0; nt < 8; nt++)
#pragma unroll
            for (int i = 0; i < 4; i++) acc[mt][nt][i] = 0.0f;

    for (int kc = 0; kc < 16; kc++) {
        const int buf = kc & 1;
#pragma unroll
        for (int q = 0; q < 8; q++)
            Aw[q] = hilo(xv[q].x * zv[q].x, xv[q].y * zv[q].y);

        if (kc < 15) {
#pragma unroll
            for (int q = 0; q < 8; q++) {
                int off = arow[q] * II + 2 * ((kc + 1) * 8 + ak2r[q]);
                xv[q] = *(const float2*)(xs + off);
                zv[q] = *(const float2*)(zxg + off);
            }
#pragma unroll
            for (int j = 0; j < 4; j++)
                Bn[j] = __ldcg(WBbase + (size_t)((kc + 1) * 8 + j) * 512);
            // store next B into the other buffer (no readers there)
#pragma unroll
            for (int j = 0; j < 4; j++) Bs[buf ^ 1][bcol * 9 + bk2 + j] = Bn[j];
        }

#pragma unroll
        for (int nt = 0; nt < 8; nt++) {
            int colg = wn * 64 + nt * 8 + gq;
            uint2 b0 = Bs[buf][colg * 9 + t];
            uint2 b1 = Bs[buf][colg * 9 + t + 4];
#pragma unroll
            for (int mt = 0; mt < 2; mt++) {
                unsigned h0 = Aw[mt*4+0].x, h1 = Aw[mt*4+1].x, h2 = Aw[mt*4+2].x, h3 = Aw[mt*4+3].x;
                unsigned l0 = Aw[mt*4+0].y, l1 = Aw[mt*4+1].y, l2 = Aw[mt*4+2].y, l3 = Aw[mt*4+3].y;
                mma16816(acc[mt][nt], h0, h1, h2, h3, b0.x, b1.x);  // hi*hi
                mma16816(acc[mt][nt], h0, h1, h2, h3, b0.y, b1.y);  // hi*lo
                mma16816(acc[mt][nt], l0, l1, l2, l3, b0.x, b1.x);  // lo*hi
            }
        }
        if (kc < 15) __syncthreads();
    }

    const float* bias = P.bx[g];
    float* outb = g_xproj + (((size_t)s * GG + g) * BB) * HH + nb;
#pragma unroll
    for (int nt = 0; nt < 8; nt++) {
        int col = wn * 64 + nt * 8 + 2 * t;
        float b0 = bias[nb + col], b1 = bias[nb + col + 1];
#pragma unroll
        for (int mt = 0; mt < 2; mt++) {
            int r = R + mt * 16 + gq;
            *(float2*)(outb + (size_t)r * HH + col) =
                make_float2(acc[mt][nt][0] + b0, acc[mt][nt][1] + b1);
            *(float2*)(outb + (size_t)(r + 8) * HH + col) =
                make_float2(acc[mt][nt][2] + b0, acc[mt][nt][3] + b1);
        }
    }
}

// ---------------------------------------------------------------------------
// Grid barrier
// ---------------------------------------------------------------------------
__device__ __forceinline__ void gbar(unsigned target) {
    __syncthreads();
    if (threadIdx.x == 0) {
        __threadfence();
        unsigned a = atomicAdd(&g_cnt, 1u);
        if (a == NCTA - 1u) {
            g_cnt = 0u;
            __threadfence();
            atomicExch(&g_gen, target);
        } else {
            while (*((volatile unsigned*)&g_gen) < target) __nanosleep(32);
            __threadfence();
        }
    }
    __syncthreads();
}

// ---------------------------------------------------------------------------
// Kernel 3: persistent recurrence — fused GEMM+update, ONE barrier per step.
// CTA (ks = cta>>2, Mq = cta&3): all 4 gates, k-cols k0=ks*16..+16,
// b-rows rb=Mq*32..+32. Warps: gw = w&3 (gate), kh = w>>2 (K half of 256).
// U fragments for all 4 gates in SMEM (128 KB). Split-K reduced in SMEM.
// Update done in-CTA (c-state in registers); hm written coalesced in
// A-fragment layout via an SMEM h-transpose tile.
// ---------------------------------------------------------------------------
__global__ __launch_bounds__(256, 1) void k_recur(Ptrs P,
        const float* __restrict__ p_logit, const float* __restrict__ uh,
        float* __restrict__ out) {
    extern __shared__ char smraw[];
    uint2* Wsm = (uint2*)smraw;                         // [g4][kh2][kk16][slot4][lane32] 128 KB
    float* preS = (float*)(smraw + 131072);             // [kh2][g4][b32][18]
    float* hS   = preS + 2 * 4 * 32 * 18;               // [b32][18]

    const int tid = threadIdx.x;
    const int cta = blockIdx.x;
    const int ks = cta >> 2, Mq = cta & 3;
    const int k0 = ks * 16;
    const int rb = Mq * 32;
    const int w = tid >> 5, lane = tid & 31;
    const int gw = w & 3, kh = w >> 2;
    const int gq = lane >> 2, t = lane & 3;

    // ---- pack persistent U fragments (all 4 gates, this k-slice), once ----
    for (int idx = tid; idx < 16384; idx += 256) {
        int l    = idx & 31;
        int slot = (idx >> 5) & 3;
        int kk   = (idx >> 7) & 15;
        int khp  = (idx >> 11) & 1;
        int g    = idx >> 12;
        int reg = slot & 1, nt = slot >> 1;
        int h   = khp * 256 + kk * 16 + reg * 8 + (l & 3) * 2;
        int col = k0 + nt * 8 + (l >> 2);
        const float* __restrict__ U = P.U[g];
        Wsm[idx] = hilo(U[(size_t)col * HH + h], U[(size_t)col * HH + h + 1]);
    }

    // ---- update-phase constants ----
    // mapping A (gate update, coalesced out): bl = tid>>3, uk = (tid&7)*2
    const int blA = tid >> 3;
    const int ukA = (tid & 7) * 2;
    const int bA  = rb + blA;
    const int kA  = k0 + ukA;
    // mapping B (hm writes, coalesced over b): blB = tid&31, kp = tid>>5
    const int blB = tid & 31;
    const int kpB = tid >> 5;
    const int bB  = rb + blB;
    const int h2B = (k0 >> 1) + kpB;
    const int kB  = k0 + kpB * 2;

    float bu_r[GG][2], zhB[GG][2];
    {
        float p = sigf(p_logit[0]);
        float lp = logf(p + EPSF) - logf(1.0f - p + EPSF);
        float inv = 1.0f / (1.0f - p);
#pragma unroll
        for (int g = 0; g < GG; g++) {
#pragma unroll
            for (int j = 0; j < 2; j++) {
                bu_r[g][j] = P.bu[g][kA + j];
                float u = uh[((size_t)g * BB + bB) * HH + kB + j];
                float sgm = sigf((lp + logf(u + EPSF) - logf(1.0f - u + EPSF)) * 10.0f);
                zhB[g][j] = (1.0f - sgm) * inv;
            }
            g_hmA[((size_t)g * 256 + h2B) * BB + bB] = make_uint2(0u, 0u);  // h0 = 0
        }
    }
    float c0 = 0.0f, c1 = 0.0f;

    __syncthreads();
    unsigned bt = 0;
    gbar(++bt);   // hm zeros + all CTAs' U packing state settled

    // A-fragment base for this warp (gate gw, K-half kh)
    const uint2* __restrict__ Abase =
        g_hmA + ((size_t)(gw * 256 + kh * 128 + t)) * BB + rb + gq;

    for (int s = 0; s < SS; s++) {
        // prefetch xproj for the update elements (mapping A)
        float2 xp[GG];
#pragma unroll
        for (int g = 0; g < GG; g++)
            xp[g] = *(const float2*)&g_xproj[(((size_t)s * GG + g) * BB + bA) * HH + kA];

        // ---------------- GEMM: pre[gw][rb..rb+32][k0..k0+16], K-half kh ----
        float acc[2][2][4];
#pragma unroll
        for (int mt = 0; mt < 2; mt++)
#pragma unroll
            for (int nt = 0; nt < 2; nt++)
#pragma unroll
                for (int i = 0; i < 4; i++) acc[mt][nt][i] = 0.0f;

        uint2 Ab[3][8];   // 3-stage ring, 8 words (2 mt x 4)
#pragma unroll
        for (int pf = 0; pf < 2; pf++) {
            const uint2* q = Abase + (size_t)pf * 1024;
#pragma unroll
            for (int mt = 0; mt < 2; mt++) {
                Ab[pf][mt * 4 + 0] = __ldcg(q + mt * 16);
                Ab[pf][mt * 4 + 1] = __ldcg(q + mt * 16 + 8);
                Ab[pf][mt * 4 + 2] = __ldcg(q + mt * 16 + 512);
                Ab[pf][mt * 4 + 3] = __ldcg(q + mt * 16 + 520);
            }
        }

#pragma unroll
        for (int kk = 0; kk < 16; kk++) {
            const int cur = kk % 3;
            if (kk < 14) {
                const int nxt = (kk + 2) % 3;
                const uint2* q = Abase + (size_t)(kk + 2) * 1024;
#pragma unroll
                for (int mt = 0; mt < 2; mt++) {
                    Ab[nxt][mt * 4 + 0] = __ldcg(q + mt * 16);
                    Ab[nxt][mt * 4 + 1] = __ldcg(q + mt * 16 + 8);
                    Ab[nxt][mt * 4 + 2] = __ldcg(q + mt * 16 + 512);
                    Ab[nxt][mt * 4 + 3] = __ldcg(q + mt * 16 + 520);
                }
            }
            const uint2* Wp = &Wsm[(((gw * 2 + kh) * 16 + kk) * 4) * 32 + lane];
#pragma unroll
            for (int nt = 0; nt < 2; nt++) {
                uint2 wb0 = Wp[(nt * 2 + 0) * 32];
                uint2 wb1 = Wp[(nt * 2 + 1) * 32];
#pragma unroll
                for (int mt = 0; mt < 2; mt++) {
                    unsigned ah0 = Ab[cur][mt*4+0].x, ah1 = Ab[cur][mt*4+1].x;
                    unsigned ah2 = Ab[cur][mt*4+2].x, ah3 = Ab[cur][mt*4+3].x;
                    unsigned al0 = Ab[cur][mt*4+0].y, al1 = Ab[cur][mt*4+1].y;
                    unsigned al2 = Ab[cur][mt*4+2].y, al3 = Ab[cur][mt*4+3].y;
                    mma16816(acc[mt][nt], ah0, ah1, ah2, ah3, wb0.x, wb1.x);  // hi*hi
                    mma16816(acc[mt][nt], ah0, ah1, ah2, ah3, wb0.y, wb1.y);  // hi*lo
                    mma16816(acc[mt][nt], al0, al1, al2, al3, wb0.x, wb1.x);  // lo*hi
                }
            }
        }

        // split-K partials -> SMEM
#pragma unroll
        for (int mt = 0; mt < 2; mt++)
#pragma unroll
            for (int nt = 0; nt < 2; nt++) {
                int b0 = mt * 16 + gq;
                int col = nt * 8 + 2 * t;
                float* pp = &preS[((kh * 4 + gw) * 32 + b0) * 18 + col];
                *(float2*)pp = make_float2(acc[mt][nt][0], acc[mt][nt][1]);
                *(float2*)(pp + 8 * 18) = make_float2(acc[mt][nt][2], acc[mt][nt][3]);
            }
        __syncthreads();

        // ---------------- Update (in-CTA), mapping A -----------------------
        float h0, h1;
        {
            float pre[GG][2];
#pragma unroll
            for (int g = 0; g < GG; g++) {
                float2 pa = *(float2*)&preS[((0 * 4 + g) * 32 + blA) * 18 + ukA];
                float2 pb = *(float2*)&preS[((1 * 4 + g) * 32 + blA) * 18 + ukA];
                pre[g][0] = pa.x + pb.x + bu_r[g][0] + xp[g].x;
                pre[g][1] = pa.y + pb.y + bu_r[g][1] + xp[g].y;
            }
            float i0 = sigf(pre[0][0]), i1 = sigf(pre[0][1]);
            float f0 = sigf(pre[1][0]), f1 = sigf(pre[1][1]);
            float o0 = sigf(pre[2][0]), o1 = sigf(pre[2][1]);
            float gg0 = tanhf(pre[3][0]), gg1 = tanhf(pre[3][1]);
            c0 = f0 * c0 + i0 * gg0;
            c1 = f1 * c1 + i1 * gg1;
            h0 = o0 * tanhf(c0);
            h1 = o1 * tanhf(c1);
        }
        *(float2*)&out[(size_t)s * BB * HH + (size_t)bA * HH + kA] = make_float2(h0, h1);
        if (s == SS - 1) {
            *(float2*)&out[(size_t)SS * BB * HH + (size_t)bA * HH + kA] = make_float2(h0, h1);
            *(float2*)&out[(size_t)(SS + 1) * BB * HH + (size_t)bA * HH + kA] = make_float2(c0, c1);
        }
        hS[blA * 18 + ukA]     = h0;
        hS[blA * 18 + ukA + 1] = h1;
        __syncthreads();

        // ---------------- hm writes, mapping B (coalesced over b) ----------
        {
            float hv0 = hS[blB * 18 + kpB * 2];
            float hv1 = hS[blB * 18 + kpB * 2 + 1];
#pragma unroll
            for (int g = 0; g < GG; g++)
                g_hmA[((size_t)g * 256 + h2B) * BB + bB] =
                    hilo(hv0 * zhB[g][0], hv1 * zhB[g][1]);
        }

        gbar(++bt);   // hm ready for next step
    }
}

// ---------------------------------------------------------------------------
extern "C" void kernel_launch(void* const* d_in, const int* in_sizes, int n_in,
                              void* d_out, int out_size) {
    const float* x       = (const float*)d_in[0];
    const float* p_logit = (const float*)d_in[1];
    Ptrs P;
    for (int g = 0; g < 4; g++) {
        P.W[g]  = (const float*)d_in[2 + 2 * g];
        P.bx[g] = (const float*)d_in[3 + 2 * g];
        P.U[g]  = (const float*)d_in[10 + 2 * g];
        P.bu[g] = (const float*)d_in[11 + 2 * g];
    }
    const float* ux = (const float*)d_in[18];
    const float* uh = (const float*)d_in[19];
    float* out = (float*)d_out;

    // Wsm 128KB + preS 2*4*32*18*4 (18432B) + hS 32*18*4 (2304B)
    const int SMEM_RECUR = 131072 + 18432 + 2304;   // 151808 B
    cudaFuncSetAttribute(k_recur, cudaFuncAttributeMaxDynamicSharedMemorySize, SMEM_RECUR);

    k_setup<<<(GG * BB * II + 255) / 256, 256>>>(p_logit, ux);
    k_pack<<<(GG * 128 * HH) / 256, 256>>>(P);
    k_xproj<<<dim3(SS, HH / 128, GG), 256>>>(x, P);
    k_recur<<<NCTA, 256, SMEM_RECUR>>>(P, p_logit, uh, out);
}

// round 12
// speedup vs baseline: 2.0614x; 1.0085x over previous
#include <cuda_runtime.h>
#include <cuda_bf16.h>
#include <math.h>

#define SS 256
#define BB 128
#define II 256
#define HH 512
#define GG 4
#define EPSF 1e-7f
#define NCTA 128

struct Ptrs {
    const float* W[4];
    const float* bx[4];
    const float* U[4];
    const float* bu[4];
};

__device__ float g_zx[GG * BB * II];
__device__ uint2 g_hmA[GG * 256 * BB];
__device__ uint2 g_WB[GG * 128 * HH];
__device__ uint2 g_xA[(size_t)SS * GG * 128 * BB];
__device__ float g_xproj[(size_t)SS * GG * BB * HH];
__device__ unsigned g_cntM[4];
__device__ unsigned g_genM[4];

__device__ __forceinline__ float sigf(float x) { return 1.0f / (1.0f + expf(-x)); }

__device__ __forceinline__ unsigned pk2(float a, float b) {
    return (unsigned)__bfloat16_as_ushort(__float2bfloat16_rn(a)) |
           ((unsigned)__bfloat16_as_ushort(__float2bfloat16_rn(b)) << 16);
}
__device__ __forceinline__ uint2 hilo(float a, float b) {
    __nv_bfloat16 ha = __float2bfloat16_rn(a);
    __nv_bfloat16 hb = __float2bfloat16_rn(b);
    unsigned hi = (unsigned)__bfloat16_as_ushort(ha) |
                  ((unsigned)__bfloat16_as_ushort(hb) << 16);
    return make_uint2(hi, pk2(a - __bfloat162float(ha), b - __bfloat162float(hb)));
}

__device__ __forceinline__ void mma16816(float* c,
        unsigned a0, unsigned a1, unsigned a2, unsigned a3,
        unsigned b0, unsigned b1) {
    asm volatile(
        "mma.sync.aligned.m16n8k16.row.col.f32.bf16.bf16.f32 "
        "{%0,%1,%2,%3}, {%4,%5,%6,%7}, {%8,%9}, {%0,%1,%2,%3};"
        : "+f"(c[0]), "+f"(c[1]), "+f"(c[2]), "+f"(c[3])
        : "r"(a0), "r"(a1), "r"(a2), "r"(a3), "r"(b0), "r"(b1));
}

// zx masks + reset barrier state (runs every replay)
__global__ void k_setup(const float* __restrict__ p_logit,
                        const float* __restrict__ ux) {
    int i = blockIdx.x * blockDim.x + threadIdx.x;
    if (i == 0) {
#pragma unroll
        for (int m = 0; m < 4; m++) { g_cntM[m] = 0u; g_genM[m] = 0u; }
    }
    if (i < GG * BB * II) {
        float p = sigf(p_logit[0]);
        float lp = logf(p + EPSF) - logf(1.0f - p + EPSF);
        float inv = 1.0f / (1.0f - p);
        float u = ux[i];
        float s = sigf((lp + logf(u + EPSF) - logf(1.0f - u + EPSF)) * 10.0f);
        g_zx[i] = (1.0f - s) * inv;
    }
}

// pack W into B-fragment hi/lo words
__global__ void k_pack(Ptrs P) {
    int idx = blockIdx.x * blockDim.x + threadIdx.x;
    int g = idx >> 16;
    int r = idx & 65535;
    int k2 = r >> 9;
    int h = r & 511;
    const float* Wg = P.W[g];
    g_WB[idx] = hilo(Wg[h * II + 2 * k2], Wg[h * II + 2 * k2 + 1]);
}

// convert A = x*zx to hi/lo fragment words once per (s,g)
__global__ void k_aconv(const float* __restrict__ x) {
    const int s = blockIdx.x, g = blockIdx.y;
    const float* __restrict__ xs  = x + (size_t)s * BB * II;
    const float* __restrict__ zxg = g_zx + (size_t)g * BB * II;
    uint2* __restrict__ outp = g_xA + (size_t)(s * GG + g) * 128 * BB;

    const int i2g = threadIdx.x >> 5;
    const int lane = threadIdx.x & 31;
#pragma unroll 4
    for (int i2 = i2g * 16; i2 < i2g * 16 + 16; i2++) {
#pragma unroll
        for (int q = 0; q < 4; q++) {
            int b = q * 32 + lane;
            float2 xv = *(const float2*)(xs + (size_t)b * II + 2 * i2);
            float2 zv = *(const float2*)(zxg + (size_t)b * II + 2 * i2);
            outp[i2 * BB + b] = hilo(xv.x * zv.x, xv.y * zv.y);
        }
    }
}

// xproj via bf16x3 mma, A fragments from g_xA. grid=(S,4,G), 256 thr.
__global__ __launch_bounds__(256, 1) void k_xproj(Ptrs P) {
    __shared__ uint2 Bs[2][128 * 9];

    const int s  = blockIdx.x;
    const int nb = blockIdx.y * 128;
    const int g  = blockIdx.z;

    const int tid = threadIdx.x;
    const int w = tid >> 5, lane = tid & 31;
    const int wm = w & 3, wn = w >> 2;
    const int gq = lane >> 2, t = lane & 3;
    const int R = wm * 32;

    const int bcol = tid & 127;
    const int bk2  = (tid >> 7) * 4;
    const uint2* __restrict__ WBbase = g_WB + ((size_t)g * 128 + bk2) * 512 + nb + bcol;
    const uint2* __restrict__ Axbase =
        g_xA + ((size_t)(s * GG + g) * 128 + t) * BB + R + gq;

    uint2 Bn[4];
    uint2 Ab[3][8];

#pragma unroll
    for (int j = 0; j < 4; j++) Bn[j] = __ldcg(WBbase + (size_t)j * 512);
#pragma unroll
    for (int j = 0; j < 4; j++) Bs[0][bcol * 9 + bk2 + j] = Bn[j];
#pragma unroll
    for (int pf = 0; pf < 2; pf++) {
        const uint2* q = Axbase + (size_t)pf * 1024;
#pragma unroll
        for (int mt = 0; mt < 2; mt++) {
            Ab[pf][mt * 4 + 0] = __ldcg(q + mt * 16);
            Ab[pf][mt * 4 + 1] = __ldcg(q + mt * 16 + 8);
            Ab[pf][mt * 4 + 2] = __ldcg(q + mt * 16 + 512);
            Ab[pf][mt * 4 + 3] = __ldcg(q + mt * 16 + 520);
        }
    }
    __syncthreads();

    float acc[2][8][4];
#pragma unroll
    for (int mt = 0; mt < 2; mt++)
#pragma unroll
        for (int nt = 0; nt < 8; nt++)
#pragma unroll
            for (int i = 0; i < 4; i++) acc[mt][nt][i] = 0.0f;

    for (int kc = 0; kc < 16; kc++) {
        const int buf = kc & 1;
        const int cur = kc % 3;
        if (kc < 15) {
#pragma unroll
            for (int j = 0; j < 4; j++)
                Bn[j] = __ldcg(WBbase + (size_t)((kc + 1) * 8 + j) * 512);
#pragma unroll
            for (int j = 0; j < 4; j++) Bs[buf ^ 1][bcol * 9 + bk2 + j] = Bn[j];
        }
        if (kc < 14) {
            const int nxt = (kc + 2) % 3;
            const uint2* q = Axbase + (size_t)(kc + 2) * 1024;
#pragma unroll
            for (int mt = 0; mt < 2; mt++) {
                Ab[nxt][mt * 4 + 0] = __ldcg(q + mt * 16);
                Ab[nxt][mt * 4 + 1] = __ldcg(q + mt * 16 + 8);
                Ab[nxt][mt * 4 + 2] = __ldcg(q + mt * 16 + 512);
                Ab[nxt][mt * 4 + 3] = __ldcg(q + mt * 16 + 520);
            }
        }

#pragma unroll
        for (int nt = 0; nt < 8; nt++) {
            int colg = wn * 64 + nt * 8 + gq;
            uint2 b0 = Bs[buf][colg * 9 + t];
            uint2 b1 = Bs[buf][colg * 9 + t + 4];
#pragma unroll
            for (int mt = 0; mt < 2; mt++) {
                unsigned h0 = Ab[cur][mt*4+0].x, h1 = Ab[cur][mt*4+1].x;
                unsigned h2 = Ab[cur][mt*4+2].x, h3 = Ab[cur][mt*4+3].x;
                unsigned l0 = Ab[cur][mt*4+0].y, l1 = Ab[cur][mt*4+1].y;
                unsigned l2 = Ab[cur][mt*4+2].y, l3 = Ab[cur][mt*4+3].y;
                mma16816(acc[mt][nt], h0, h1, h2, h3, b0.x, b1.x);
                mma16816(acc[mt][nt], h0, h1, h2, h3, b0.y, b1.y);
                mma16816(acc[mt][nt], l0, l1, l2, l3, b0.x, b1.x);
            }
        }
        if (kc < 15) __syncthreads();
    }

    const float* bias = P.bx[g];
    float* outb = g_xproj + (((size_t)s * GG + g) * BB) * HH + nb;
#pragma unroll
    for (int nt = 0; nt < 8; nt++) {
        int col = wn * 64 + nt * 8 + 2 * t;
        float b0 = bias[nb + col], b1 = bias[nb + col + 1];
#pragma unroll
        for (int mt = 0; mt < 2; mt++) {
            int r = R + mt * 16 + gq;
            *(float2*)(outb + (size_t)r * HH + col) =
                make_float2(acc[mt][nt][0] + b0, acc[mt][nt][1] + b1);
            *(float2*)(outb + (size_t)(r + 8) * HH + col) =
                make_float2(acc[mt][nt][2] + b0, acc[mt][nt][3] + b1);
        }
    }
}

// per-Mq-group barrier (4 independent groups of 32 CTAs)
__device__ __forceinline__ void gbarM(int m, unsigned target) {
    __syncthreads();
    if (threadIdx.x == 0) {
        __threadfence();
        unsigned a = atomicAdd(&g_cntM[m], 1u);
        if (a == 31u) {
            g_cntM[m] = 0u;
            __threadfence();
            atomicExch(&g_genM[m], target);
        } else {
            while (*((volatile unsigned*)&g_genM[m]) < target) __nanosleep(32);
            __threadfence();
        }
    }
    __syncthreads();
}

// persistent recurrence: fused GEMM + update, one group barrier per step.
__global__ __launch_bounds__(256, 1) void k_recur(Ptrs P,
        const float* __restrict__ p_logit, const float* __restrict__ uh,
        float* __restrict__ out) {
    extern __shared__ char smraw[];
    uint2* Wsm = (uint2*)smraw;                  // 128 KB
    float* preS = (float*)(smraw + 131072);      // [kh2][g4][b32][18]
    float* hS   = preS + 2 * 4 * 32 * 18;        // [b32][18]

    const int tid = threadIdx.x;
    const int cta = blockIdx.x;
    const int ks = cta >> 2, Mq = cta & 3;
    const int k0 = ks * 16;
    const int rb = Mq * 32;
    const int w = tid >> 5, lane = tid & 31;
    const int gw = w & 3, kh = w >> 2;
    const int gq = lane >> 2, t = lane & 3;

    for (int idx = tid; idx < 16384; idx += 256) {
        int l    = idx & 31;
        int slot = (idx >> 5) & 3;
        int kk   = (idx >> 7) & 15;
        int khp  = (idx >> 11) & 1;
        int g    = idx >> 12;
        int reg = slot & 1, nt = slot >> 1;
        int h   = khp * 256 + kk * 16 + reg * 8 + (l & 3) * 2;
        int col = k0 + nt * 8 + (l >> 2);
        const float* __restrict__ U = P.U[g];
        Wsm[idx] = hilo(U[(size_t)col * HH + h], U[(size_t)col * HH + h + 1]);
    }

    const int blA = tid >> 3;
    const int ukA = (tid & 7) * 2;
    const int bA  = rb + blA;
    const int kA  = k0 + ukA;
    const int blB = tid & 31;
    const int kpB = tid >> 5;
    const int bB  = rb + blB;
    const int h2B = (k0 >> 1) + kpB;
    const int kB  = k0 + kpB * 2;

    float bu_r[GG][2], zhB[GG][2];
    {
        float p = sigf(p_logit[0]);
        float lp = logf(p + EPSF) - logf(1.0f - p + EPSF);
        float inv = 1.0f / (1.0f - p);
#pragma unroll
        for (int g = 0; g < GG; g++) {
#pragma unroll
            for (int j = 0; j < 2; j++) {
                bu_r[g][j] = P.bu[g][kA + j];
                float u = uh[((size_t)g * BB + bB) * HH + kB + j];
                float sgm = sigf((lp + logf(u + EPSF) - logf(1.0f - u + EPSF)) * 10.0f);
                zhB[g][j] = (1.0f - sgm) * inv;
            }
            g_hmA[((size_t)g * 256 + h2B) * BB + bB] = make_uint2(0u, 0u);
        }
    }
    float c0 = 0.0f, c1 = 0.0f;

    __syncthreads();
    unsigned bt = 0;
    gbarM(Mq, ++bt);

    const uint2* __restrict__ Abase =
        g_hmA + ((size_t)(gw * 256 + kh * 128 + t)) * BB + rb + gq;

    for (int s = 0; s < SS; s++) {
        float2 xp[GG];
#pragma unroll
        for (int g = 0; g < GG; g++)
            xp[g] = *(const float2*)&g_xproj[(((size_t)s * GG + g) * BB + bA) * HH + kA];

        float acc[2][2][4];
#pragma unroll
        for (int mt = 0; mt < 2; mt++)
#pragma unroll
            for (int nt = 0; nt < 2; nt++)
#pragma unroll
                for (int i = 0; i < 4; i++) acc[mt][nt][i] = 0.0f;

        uint2 Ab[4][8];
#pragma unroll
        for (int pf = 0; pf < 3; pf++) {
            const uint2* q = Abase + (size_t)pf * 1024;
#pragma unroll
            for (int mt = 0; mt < 2; mt++) {
                Ab[pf][mt * 4 + 0] = __ldcg(q + mt * 16);
                Ab[pf][mt * 4 + 1] = __ldcg(q + mt * 16 + 8);
                Ab[pf][mt * 4 + 2] = __ldcg(q + mt * 16 + 512);
                Ab[pf][mt * 4 + 3] = __ldcg(q + mt * 16 + 520);
            }
        }

#pragma unroll
        for (int kk = 0; kk < 16; kk++) {
            const int cur = kk & 3;
            if (kk < 13) {
                const int nxt = (kk + 3) & 3;
                const uint2* q = Abase + (size_t)(kk + 3) * 1024;
#pragma unroll
                for (int mt = 0; mt < 2; mt++) {
                    Ab[nxt][mt * 4 + 0] = __ldcg(q + mt * 16);
                    Ab[nxt][mt * 4 + 1] = __ldcg(q + mt * 16 + 8);
                    Ab[nxt][mt * 4 + 2] = __ldcg(q + mt * 16 + 512);
                    Ab[nxt][mt * 4 + 3] = __ldcg(q + mt * 16 + 520);
                }
            }
            const uint2* Wp = &Wsm[(((gw * 2 + kh) * 16 + kk) * 4) * 32 + lane];
#pragma unroll
            for (int nt = 0; nt < 2; nt++) {
                uint2 wb0 = Wp[(nt * 2 + 0) * 32];
                uint2 wb1 = Wp[(nt * 2 + 1) * 32];
#pragma unroll
                for (int mt = 0; mt < 2; mt++) {
                    unsigned ah0 = Ab[cur][mt*4+0].x, ah1 = Ab[cur][mt*4+1].x;
                    unsigned ah2 = Ab[cur][mt*4+2].x, ah3 = Ab[cur][mt*4+3].x;
                    unsigned al0 = Ab[cur][mt*4+0].y, al1 = Ab[cur][mt*4+1].y;
                    unsigned al2 = Ab[cur][mt*4+2].y, al3 = Ab[cur][mt*4+3].y;
                    mma16816(acc[mt][nt], ah0, ah1, ah2, ah3, wb0.x, wb1.x);
                    mma16816(acc[mt][nt], ah0, ah1, ah2, ah3, wb0.y, wb1.y);
                    mma16816(acc[mt][nt], al0, al1, al2, al3, wb0.x, wb1.x);
                }
            }
        }

#pragma unroll
        for (int mt = 0; mt < 2; mt++)
#pragma unroll
            for (int nt = 0; nt < 2; nt++) {
                int b0 = mt * 16 + gq;
                int col = nt * 8 + 2 * t;
                float* pp = &preS[((kh * 4 + gw) * 32 + b0) * 18 + col];
                *(float2*)pp = make_float2(acc[mt][nt][0], acc[mt][nt][1]);
                *(float2*)(pp + 8 * 18) = make_float2(acc[mt][nt][2], acc[mt][nt][3]);
            }
        __syncthreads();

        float h0, h1;
        {
            float pre[GG][2];
#pragma unroll
            for (int g = 0; g < GG; g++) {
                float2 pa = *(float2*)&preS[((0 * 4 + g) * 32 + blA) * 18 + ukA];
                float2 pb = *(float2*)&preS[((1 * 4 + g) * 32 + blA) * 18 + ukA];
                pre[g][0] = pa.x + pb.x + bu_r[g][0] + xp[g].x;
                pre[g][1] = pa.y + pb.y + bu_r[g][1] + xp[g].y;
            }
            float i0 = sigf(pre[0][0]), i1 = sigf(pre[0][1]);
            float f0 = sigf(pre[1][0]), f1 = sigf(pre[1][1]);
            float o0 = sigf(pre[2][0]), o1 = sigf(pre[2][1]);
            float gg0 = tanhf(pre[3][0]), gg1 = tanhf(pre[3][1]);
            c0 = f0 * c0 + i0 * gg0;
            c1 = f1 * c1 + i1 * gg1;
            h0 = o0 * tanhf(c0);
            h1 = o1 * tanhf(c1);
        }
        *(float2*)&out[(size_t)s * BB * HH + (size_t)bA * HH + kA] = make_float2(h0, h1);
        if (s == SS - 1) {
            *(float2*)&out[(size_t)SS * BB * HH + (size_t)bA * HH + kA] = make_float2(h0, h1);
            *(float2*)&out[(size_t)(SS + 1) * BB * HH + (size_t)bA * HH + kA] = make_float2(c0, c1);
        }
        hS[blA * 18 + ukA]     = h0;
        hS[blA * 18 + ukA + 1] = h1;
        __syncthreads();

        {
            float hv0 = hS[blB * 18 + kpB * 2];
            float hv1 = hS[blB * 18 + kpB * 2 + 1];
#pragma unroll
            for (int g = 0; g < GG; g++)
                g_hmA[((size_t)g * 256 + h2B) * BB + bB] =
                    hilo(hv0 * zhB[g][0], hv1 * zhB[g][1]);
        }

        gbarM(Mq, ++bt);
    }
}

extern "C" void kernel_launch(void* const* d_in, const int* in_sizes, int n_in,
                              void* d_out, int out_size) {
    const float* x       = (const float*)d_in[0];
    const float* p_logit = (const float*)d_in[1];
    Ptrs P;
    for (int g = 0; g < 4; g++) {
        P.W[g]  = (const float*)d_in[2 + 2 * g];
        P.bx[g] = (const float*)d_in[3 + 2 * g];
        P.U[g]  = (const float*)d_in[10 + 2 * g];
        P.bu[g] = (const float*)d_in[11 + 2 * g];
    }
    const float* ux = (const float*)d_in[18];
    const float* uh = (const float*)d_in[19];
    float* out = (float*)d_out;

    const int SMEM_RECUR = 131072 + 18432 + 2304;
    cudaFuncSetAttribute(k_recur, cudaFuncAttributeMaxDynamicSharedMemorySize, SMEM_RECUR);

    k_setup<<<(GG * BB * II + 255) / 256, 256>>>(p_logit, ux);
    k_pack<<<(GG * 128 * HH) / 256, 256>>>(P);
    k_aconv<<<dim3(SS, GG), 256>>>(x);
    k_xproj<<<dim3(SS, HH / 128, GG), 256>>>(P);
    k_recur<<<NCTA, 256, SMEM_RECUR>>>(P, p_logit, uh, out);
}

// round 16
// speedup vs baseline: 2.1387x; 1.0375x over previous
#include <cuda_runtime.h>
#include <cuda_bf16.h>
#include <math.h>

#define SS 256
#define BB 128
#define II 256
#define HH 512
#define GG 4
#define EPSF 1e-7f
#define NCTA 128

struct Ptrs {
    const float* W[4];
    const float* bx[4];
    const float* U[4];
    const float* bu[4];
};

__device__ float g_zx[GG * BB * II];
__device__ uint2 g_hmA[GG * 256 * BB];
__device__ uint2 g_WB[GG * 128 * HH];
__device__ uint2 g_xA[(size_t)SS * GG * 128 * BB];
__device__ float g_xproj[(size_t)SS * GG * BB * HH];
__device__ unsigned g_cntM[4];
__device__ unsigned g_genM[4];

__device__ __forceinline__ float sigf(float x) { return 1.0f / (1.0f + expf(-x)); }

__device__ __forceinline__ unsigned pk2(float a, float b) {
    return (unsigned)__bfloat16_as_ushort(__float2bfloat16_rn(a)) |
           ((unsigned)__bfloat16_as_ushort(__float2bfloat16_rn(b)) << 16);
}
__device__ __forceinline__ uint2 hilo(float a, float b) {
    __nv_bfloat16 ha = __float2bfloat16_rn(a);
    __nv_bfloat16 hb = __float2bfloat16_rn(b);
    unsigned hi = (unsigned)__bfloat16_as_ushort(ha) |
                  ((unsigned)__bfloat16_as_ushort(hb) << 16);
    return make_uint2(hi, pk2(a - __bfloat162float(ha), b - __bfloat162float(hb)));
}

__device__ __forceinline__ void mma16816(float* c,
        unsigned a0, unsigned a1, unsigned a2, unsigned a3,
        unsigned b0, unsigned b1) {
    asm volatile(
        "mma.sync.aligned.m16n8k16.row.col.f32.bf16.bf16.f32 "
        "{%0,%1,%2,%3}, {%4,%5,%6,%7}, {%8,%9}, {%0,%1,%2,%3};"
        : "+f"(c[0]), "+f"(c[1]), "+f"(c[2]), "+f"(c[3])
        : "r"(a0), "r"(a1), "r"(a2), "r"(a3), "r"(b0), "r"(b1));
}

// zx masks + reset barrier state (runs every replay)
__global__ void k_setup(const float* __restrict__ p_logit,
                        const float* __restrict__ ux) {
    int i = blockIdx.x * blockDim.x + threadIdx.x;
    if (i == 0) {
#pragma unroll
        for (int m = 0; m < 4; m++) { g_cntM[m] = 0u; g_genM[m] = 0u; }
    }
    if (i < GG * BB * II) {
        float p = sigf(p_logit[0]);
        float lp = logf(p + EPSF) - logf(1.0f - p + EPSF);
        float inv = 1.0f / (1.0f - p);
        float u = ux[i];
        float s = sigf((lp + logf(u + EPSF) - logf(1.0f - u + EPSF)) * 10.0f);
        g_zx[i] = (1.0f - s) * inv;
    }
}

// pack W into B-fragment hi/lo words
__global__ void k_pack(Ptrs P) {
    int idx = blockIdx.x * blockDim.x + threadIdx.x;
    int g = idx >> 16;
    int r = idx & 65535;
    int k2 = r >> 9;
    int h = r & 511;
    const float* Wg = P.W[g];
    g_WB[idx] = hilo(Wg[h * II + 2 * k2], Wg[h * II + 2 * k2 + 1]);
}

// convert A = x*zx to hi/lo fragment words once per (s,g)
__global__ void k_aconv(const float* __restrict__ x) {
    const int s = blockIdx.x, g = blockIdx.y;
    const float* __restrict__ xs  = x + (size_t)s * BB * II;
    const float* __restrict__ zxg = g_zx + (size_t)g * BB * II;
    uint2* __restrict__ outp = g_xA + (size_t)(s * GG + g) * 128 * BB;

    const int i2g = threadIdx.x >> 5;
    const int lane = threadIdx.x & 31;
#pragma unroll 4
    for (int i2 = i2g * 16; i2 < i2g * 16 + 16; i2++) {
#pragma unroll
        for (int q = 0; q < 4; q++) {
            int b = q * 32 + lane;
            float2 xv = *(const float2*)(xs + (size_t)b * II + 2 * i2);
            float2 zv = *(const float2*)(zxg + (size_t)b * II + 2 * i2);
            outp[i2 * BB + b] = hilo(xv.x * zv.x, xv.y * zv.y);
        }
    }
}

// xproj via bf16x3 mma, A fragments from g_xA. grid=(S,4,G), 256 thr, 2 CTA/SM.
__global__ __launch_bounds__(256, 2) void k_xproj(Ptrs P) {
    __shared__ uint2 Bs[2][128 * 9];

    const int s  = blockIdx.x;
    const int nb = blockIdx.y * 128;
    const int g  = blockIdx.z;

    const int tid = threadIdx.x;
    const int w = tid >> 5, lane = tid & 31;
    const int wm = w & 3, wn = w >> 2;
    const int gq = lane >> 2, t = lane & 3;
    const int R = wm * 32;

    const int bcol = tid & 127;
    const int bk2  = (tid >> 7) * 4;
    const uint2* __restrict__ WBbase = g_WB + ((size_t)g * 128 + bk2) * 512 + nb + bcol;
    const uint2* __restrict__ Axbase =
        g_xA + ((size_t)(s * GG + g) * 128 + t) * BB + R + gq;

    uint2 Bn[4];
    uint2 Ab[3][8];

#pragma unroll
    for (int j = 0; j < 4; j++) Bn[j] = __ldcg(WBbase + (size_t)j * 512);
#pragma unroll
    for (int j = 0; j < 4; j++) Bs[0][bcol * 9 + bk2 + j] = Bn[j];
#pragma unroll
    for (int pf = 0; pf < 2; pf++) {
        const uint2* q = Axbase + (size_t)pf * 1024;
#pragma unroll
        for (int mt = 0; mt < 2; mt++) {
            Ab[pf][mt * 4 + 0] = __ldcg(q + mt * 16);
            Ab[pf][mt * 4 + 1] = __ldcg(q + mt * 16 + 8);
            Ab[pf][mt * 4 + 2] = __ldcg(q + mt * 16 + 512);
            Ab[pf][mt * 4 + 3] = __ldcg(q + mt * 16 + 520);
        }
    }
    __syncthreads();

    float acc[2][8][4];
#pragma unroll
    for (int mt = 0; mt < 2; mt++)
#pragma unroll
        for (int nt = 0; nt < 8; nt++)
#pragma unroll
            for (int i = 0; i < 4; i++) acc[mt][nt][i] = 0.0f;

    for (int kc = 0; kc < 16; kc++) {
        const int buf = kc & 1;
        const int cur = kc % 3;
        if (kc < 15) {
#pragma unroll
            for (int j = 0; j < 4; j++)
                Bn[j] = __ldcg(WBbase + (size_t)((kc + 1) * 8 + j) * 512);
#pragma unroll
            for (int j = 0; j < 4; j++) Bs[buf ^ 1][bcol * 9 + bk2 + j] = Bn[j];
        }
        if (kc < 14) {
            const int nxt = (kc + 2) % 3;
            const uint2* q = Axbase + (size_t)(kc + 2) * 1024;
#pragma unroll
            for (int mt = 0; mt < 2; mt++) {
                Ab[nxt][mt * 4 + 0] = __ldcg(q + mt * 16);
                Ab[nxt][mt * 4 + 1] = __ldcg(q + mt * 16 + 8);
                Ab[nxt][mt * 4 + 2] = __ldcg(q + mt * 16 + 512);
                Ab[nxt][mt * 4 + 3] = __ldcg(q + mt * 16 + 520);
            }
        }

#pragma unroll
        for (int nt = 0; nt < 8; nt++) {
            int colg = wn * 64 + nt * 8 + gq;
            uint2 b0 = Bs[buf][colg * 9 + t];
            uint2 b1 = Bs[buf][colg * 9 + t + 4];
#pragma unroll
            for (int mt = 0; mt < 2; mt++) {
                unsigned h0 = Ab[cur][mt*4+0].x, h1 = Ab[cur][mt*4+1].x;
                unsigned h2 = Ab[cur][mt*4+2].x, h3 = Ab[cur][mt*4+3].x;
                unsigned l0 = Ab[cur][mt*4+0].y, l1 = Ab[cur][mt*4+1].y;
                unsigned l2 = Ab[cur][mt*4+2].y, l3 = Ab[cur][mt*4+3].y;
                mma16816(acc[mt][nt], h0, h1, h2, h3, b0.x, b1.x);
                mma16816(acc[mt][nt], h0, h1, h2, h3, b0.y, b1.y);
                mma16816(acc[mt][nt], l0, l1, l2, l3, b0.x, b1.x);
            }
        }
        if (kc < 15) __syncthreads();
    }

    const float* bias = P.bx[g];
    float* outb = g_xproj + (((size_t)s * GG + g) * BB) * HH + nb;
#pragma unroll
    for (int nt = 0; nt < 8; nt++) {
        int col = wn * 64 + nt * 8 + 2 * t;
        float b0 = bias[nb + col], b1 = bias[nb + col + 1];
#pragma unroll
        for (int mt = 0; mt < 2; mt++) {
            int r = R + mt * 16 + gq;
            *(float2*)(outb + (size_t)r * HH + col) =
                make_float2(acc[mt][nt][0] + b0, acc[mt][nt][1] + b1);
            *(float2*)(outb + (size_t)(r + 8) * HH + col) =
                make_float2(acc[mt][nt][2] + b0, acc[mt][nt][3] + b1);
        }
    }
}

// per-Mq-group barrier: release via fence+atomics, consumer acquire-polls
__device__ __forceinline__ void gbarM(int m, unsigned target) {
    __syncthreads();
    if (threadIdx.x == 0) {
        __threadfence();
        unsigned a = atomicAdd(&g_cntM[m], 1u);
        if (a == 31u) {
            g_cntM[m] = 0u;
            __threadfence();
            atomicExch(&g_genM[m], target);
        } else {
            unsigned v;
            while (true) {
                asm volatile("ld.acquire.gpu.global.u32 %0, [%1];"
                             : "=r"(v) : "l"(&g_genM[m]) : "memory");
                if (v >= target) break;
                __nanosleep(20);
            }
        }
    }
    __syncthreads();
}

// persistent recurrence: fused GEMM + update, one group barrier per step.
__global__ __launch_bounds__(256, 1) void k_recur(Ptrs P,
        const float* __restrict__ p_logit, const float* __restrict__ uh,
        float* __restrict__ out) {
    extern __shared__ char smraw[];
    uint2* Wsm = (uint2*)smraw;                  // 128 KB
    float* preS = (float*)(smraw + 131072);      // [kh2][g4][b32][18]
    float* hS   = preS + 2 * 4 * 32 * 18;        // [b32][18]

    const int tid = threadIdx.x;
    const int cta = blockIdx.x;
    const int ks = cta >> 2, Mq = cta & 3;
    const int k0 = ks * 16;
    const int rb = Mq * 32;
    const int w = tid >> 5, lane = tid & 31;
    const int gw = w & 3, kh = w >> 2;
    const int gq = lane >> 2, t = lane & 3;

    for (int idx = tid; idx < 16384; idx += 256) {
        int l    = idx & 31;
        int slot = (idx >> 5) & 3;
        int kk   = (idx >> 7) & 15;
        int khp  = (idx >> 11) & 1;
        int g    = idx >> 12;
        int reg = slot & 1, nt = slot >> 1;
        int h   = khp * 256 + kk * 16 + reg * 8 + (l & 3) * 2;
        int col = k0 + nt * 8 + (l >> 2);
        const float* __restrict__ U = P.U[g];
        Wsm[idx] = hilo(U[(size_t)col * HH + h], U[(size_t)col * HH + h + 1]);
    }

    const int blA = tid >> 3;
    const int ukA = (tid & 7) * 2;
    const int bA  = rb + blA;
    const int kA  = k0 + ukA;
    const int blB = tid & 31;
    const int kpB = tid >> 5;
    const int bB  = rb + blB;
    const int h2B = (k0 >> 1) + kpB;
    const int kB  = k0 + kpB * 2;

    float bu_r[GG][2], zhB[GG][2];
    {
        float p = sigf(p_logit[0]);
        float lp = logf(p + EPSF) - logf(1.0f - p + EPSF);
        float inv = 1.0f / (1.0f - p);
#pragma unroll
        for (int g = 0; g < GG; g++) {
#pragma unroll
            for (int j = 0; j < 2; j++) {
                bu_r[g][j] = P.bu[g][kA + j];
                float u = uh[((size_t)g * BB + bB) * HH + kB + j];
                float sgm = sigf((lp + logf(u + EPSF) - logf(1.0f - u + EPSF)) * 10.0f);
                zhB[g][j] = (1.0f - sgm) * inv;
            }
            g_hmA[((size_t)g * 256 + h2B) * BB + bB] = make_uint2(0u, 0u);
        }
    }
    float c0 = 0.0f, c1 = 0.0f;

    __syncthreads();
    unsigned bt = 0;
    gbarM(Mq, ++bt);

    const uint2* __restrict__ Abase =
        g_hmA + ((size_t)(gw * 256 + kh * 128 + t)) * BB + rb + gq;

    for (int s = 0; s < SS; s++) {
        float2 xp[GG];
#pragma unroll
        for (int g = 0; g < GG; g++)
            xp[g] = *(const float2*)&g_xproj[(((size_t)s * GG + g) * BB + bA) * HH + kA];

        float acc[2][2][4];
#pragma unroll
        for (int mt = 0; mt < 2; mt++)
#pragma unroll
            for (int nt = 0; nt < 2; nt++)
#pragma unroll
                for (int i = 0; i < 4; i++) acc[mt][nt][i] = 0.0f;

        uint2 Ab[6][8];   // 6-stage ring, prefetch distance 5
#pragma unroll
        for (int pf = 0; pf < 5; pf++) {
            const uint2* q = Abase + (size_t)pf * 1024;
#pragma unroll
            for (int mt = 0; mt < 2; mt++) {
                Ab[pf][mt * 4 + 0] = __ldcg(q + mt * 16);
                Ab[pf][mt * 4 + 1] = __ldcg(q + mt * 16 + 8);
                Ab[pf][mt * 4 + 2] = __ldcg(q + mt * 16 + 512);
                Ab[pf][mt * 4 + 3] = __ldcg(q + mt * 16 + 520);
            }
        }

#pragma unroll
        for (int kk = 0; kk < 16; kk++) {
            const int cur = kk % 6;
            if (kk < 11) {
                const int nxt = (kk + 5) % 6;
                const uint2* q = Abase + (size_t)(kk + 5) * 1024;
#pragma unroll
                for (int mt = 0; mt < 2; mt++) {
                    Ab[nxt][mt * 4 + 0] = __ldcg(q + mt * 16);
                    Ab[nxt][mt * 4 + 1] = __ldcg(q + mt * 16 + 8);
                    Ab[nxt][mt * 4 + 2] = __ldcg(q + mt * 16 + 512);
                    Ab[nxt][mt * 4 + 3] = __ldcg(q + mt * 16 + 520);
                }
            }
            const uint2* Wp = &Wsm[(((gw * 2 + kh) * 16 + kk) * 4) * 32 + lane];
#pragma unroll
            for (int nt = 0; nt < 2; nt++) {
                uint2 wb0 = Wp[(nt * 2 + 0) * 32];
                uint2 wb1 = Wp[(nt * 2 + 1) * 32];
#pragma unroll
                for (int mt = 0; mt < 2; mt++) {
                    unsigned ah0 = Ab[cur][mt*4+0].x, ah1 = Ab[cur][mt*4+1].x;
                    unsigned ah2 = Ab[cur][mt*4+2].x, ah3 = Ab[cur][mt*4+3].x;
                    unsigned al0 = Ab[cur][mt*4+0].y, al1 = Ab[cur][mt*4+1].y;
                    unsigned al2 = Ab[cur][mt*4+2].y, al3 = Ab[cur][mt*4+3].y;
                    mma16816(acc[mt][nt], ah0, ah1, ah2, ah3, wb0.x, wb1.x);
                    mma16816(acc[mt][nt], ah0, ah1, ah2, ah3, wb0.y, wb1.y);
                    mma16816(acc[mt][nt], al0, al1, al2, al3, wb0.x, wb1.x);
                }
            }
        }

#pragma unroll
        for (int mt = 0; mt < 2; mt++)
#pragma unroll
            for (int nt = 0; nt < 2; nt++) {
                int b0 = mt * 16 + gq;
                int col = nt * 8 + 2 * t;
                float* pp = &preS[((kh * 4 + gw) * 32 + b0) * 18 + col];
                *(float2*)pp = make_float2(acc[mt][nt][0], acc[mt][nt][1]);
                *(float2*)(pp + 8 * 18) = make_float2(acc[mt][nt][2], acc[mt][nt][3]);
            }
        __syncthreads();

        float h0, h1;
        {
            float pre[GG][2];
#pragma unroll
            for (int g = 0; g < GG; g++) {
                float2 pa = *(float2*)&preS[((0 * 4 + g) * 32 + blA) * 18 + ukA];
                float2 pb = *(float2*)&preS[((1 * 4 + g) * 32 + blA) * 18 + ukA];
                pre[g][0] = pa.x + pb.x + bu_r[g][0] + xp[g].x;
                pre[g][1] = pa.y + pb.y + bu_r[g][1] + xp[g].y;
            }
            float i0 = sigf(pre[0][0]), i1 = sigf(pre[0][1]);
            float f0 = sigf(pre[1][0]), f1 = sigf(pre[1][1]);
            float o0 = sigf(pre[2][0]), o1 = sigf(pre[2][1]);
            float gg0 = tanhf(pre[3][0]), gg1 = tanhf(pre[3][1]);
            c0 = f0 * c0 + i0 * gg0;
            c1 = f1 * c1 + i1 * gg1;
            h0 = o0 * tanhf(c0);
            h1 = o1 * tanhf(c1);
        }
        *(float2*)&out[(size_t)s * BB * HH + (size_t)bA * HH + kA] = make_float2(h0, h1);
        if (s == SS - 1) {
            *(float2*)&out[(size_t)SS * BB * HH + (size_t)bA * HH + kA] = make_float2(h0, h1);
            *(float2*)&out[(size_t)(SS + 1) * BB * HH + (size_t)bA * HH + kA] = make_float2(c0, c1);
        }
        hS[blA * 18 + ukA]     = h0;
        hS[blA * 18 + ukA + 1] = h1;
        __syncthreads();

        {
            float hv0 = hS[blB * 18 + kpB * 2];
            float hv1 = hS[blB * 18 + kpB * 2 + 1];
#pragma unroll
            for (int g = 0; g < GG; g++)
                g_hmA[((size_t)g * 256 + h2B) * BB + bB] =
                    hilo(hv0 * zhB[g][0], hv1 * zhB[g][1]);
        }

        gbarM(Mq, ++bt);
    }
}

extern "C" void kernel_launch(void* const* d_in, const int* in_sizes, int n_in,
                              void* d_out, int out_size) {
    const float* x       = (const float*)d_in[0];
    const float* p_logit = (const float*)d_in[1];
    Ptrs P;
    for (int g = 0; g < 4; g++) {
        P.W[g]  = (const float*)d_in[2 + 2 * g];
        P.bx[g] = (const float*)d_in[3 + 2 * g];
        P.U[g]  = (const float*)d_in[10 + 2 * g];
        P.bu[g] = (const float*)d_in[11 + 2 * g];
    }
    const float* ux = (const float*)d_in[18];
    const float* uh = (const float*)d_in[19];
    float* out = (float*)d_out;

    const int SMEM_RECUR = 131072 + 18432 + 2304;
    cudaFuncSetAttribute(k_recur, cudaFuncAttributeMaxDynamicSharedMemorySize, SMEM_RECUR);

    k_setup<<<(GG * BB * II + 255) / 256, 256>>>(p_logit, ux);
    k_pack<<<(GG * 128 * HH) / 256, 256>>>(P);
    k_aconv<<<dim3(SS, GG), 256>>>(x);
    k_xproj<<<dim3(SS, HH / 128, GG), 256>>>(P);
    k_recur<<<NCTA, 256, SMEM_RECUR>>>(P, p_logit, uh, out);
}